// round 15
// baseline (speedup 1.0000x reference)
#include <cuda_runtime.h>
#include <cuda_fp16.h>

// Problem constants (fixed by the reference)
#define N_NODES 50000
#define N_EDGES 800000
#define F_IN    64
#define H       128
#define L_LAYERS 4
#define G_GRAPHS 64
#define C_OUT   10
#define TAB     256           // filter table: L1-resident
#define GAMMA_C 10.0f

// ---------------- scratch (device globals: allocation-free) ----------------
__device__ __half g_proj[N_NODES * H];
__device__ __half g_agg [N_NODES * H];
__device__ __half g_table2[L_LAYERS * TAB * 2 * H];   // interleaved (4 val, 4 delta) groups
__device__ __half g_w2t[L_LAYERS * H * H];
__device__ __half g_w1t[(L_LAYERS - 1) * H * H];
__device__ float  g_pool[G_GRAPHS * H];
__device__ float  g_cnt [G_GRAPHS];
// CSR-by-dst scratch
__device__ int    g_deg   [N_NODES];
__device__ int    g_rowptr[N_NODES + 1];
__device__ int    g_cursor[N_NODES];
__device__ int2   g_edge_s[N_EDGES];

// ---------------- small helpers ----------------
__device__ __forceinline__ float ssp(float v) {
    return fmaxf(v, 0.f) + log1pf(expf(-fabsf(v))) - 0.6931472f;
}

__device__ __forceinline__ unsigned f2tf32(float x) {
    unsigned u;
    asm("cvt.rna.tf32.f32 %0, %1;" : "=r"(u) : "f"(x));
    return u;
}

__device__ __forceinline__ void cp_async16(unsigned saddr, const void* gaddr, int szbytes) {
    asm volatile("cp.async.cg.shared.global [%0], [%1], 16, %2;"
                 :: "r"(saddr), "l"(gaddr), "r"(szbytes));
}

__device__ __forceinline__ void ldsm_x4(unsigned& r0, unsigned& r1, unsigned& r2, unsigned& r3,
                                        unsigned addr) {
    asm volatile("ldmatrix.sync.aligned.m8n8.x4.shared.b16 {%0,%1,%2,%3}, [%4];"
                 : "=r"(r0), "=r"(r1), "=r"(r2), "=r"(r3) : "r"(addr));
}

// ---------------- weight pre-transpose (fp16 [n][k]) + pool zeroing ----------------
__global__ void wtrans_kernel(const float* __restrict__ W2, const float* __restrict__ W1_rest) {
    int l = blockIdx.y;
    int i = blockIdx.x * 256 + threadIdx.x;   // 0..16383
    int k = i >> 7, n = i & 127;
    g_w2t[l * H * H + n * H + k] = __float2half_rn(W2[l * H * H + k * H + n]);
    if (l < L_LAYERS - 1)
        g_w1t[l * H * H + n * H + k] = __float2half_rn(W1_rest[l * H * H + k * H + n]);
    if (l == 0) {
        if (i < G_GRAPHS * H) g_pool[i] = 0.f;
        if (i < G_GRAPHS)     g_cnt[i]  = 0.f;
    }
}

// ---------------- CSR build ----------------
__global__ void deg_count_kernel(const int* __restrict__ dst, int E) {
    int i = blockIdx.x * blockDim.x + threadIdx.x;
    int e4 = i * 4;
    if (e4 + 3 < E) {
        int4 d = __ldg((const int4*)dst + i);
        atomicAdd(&g_deg[d.x], 1);
        atomicAdd(&g_deg[d.y], 1);
        atomicAdd(&g_deg[d.z], 1);
        atomicAdd(&g_deg[d.w], 1);
    } else {
        for (int e = e4; e < E; e++) atomicAdd(&g_deg[dst[e]], 1);
    }
}

// single-block exclusive scan of g_deg -> g_rowptr/g_cursor (1024 threads, chunked)
__global__ void scan_kernel(int N, int E) {
    const int C = (N + 1023) / 1024;
    int t = threadIdx.x;
    int lane = t & 31, w = t >> 5;
    int base = t * C;

    int sum = 0;
    for (int j = 0; j < C; j++) {
        int i = base + j;
        if (i < N) sum += g_deg[i];
    }

    __shared__ int ws[32];
    int x = sum;
    #pragma unroll
    for (int o = 1; o < 32; o <<= 1) {
        int y = __shfl_up_sync(0xffffffffu, x, o);
        if (lane >= o) x += y;
    }
    if (lane == 31) ws[w] = x;
    __syncthreads();
    if (w == 0) {
        int s = ws[lane];
        #pragma unroll
        for (int o = 1; o < 32; o <<= 1) {
            int y = __shfl_up_sync(0xffffffffu, s, o);
            if (lane >= o) s += y;
        }
        ws[lane] = s;
    }
    __syncthreads();

    int run = x - sum + ((w > 0) ? ws[w - 1] : 0);
    for (int j = 0; j < C; j++) {
        int i = base + j;
        if (i < N) {
            g_rowptr[i] = run;
            g_cursor[i] = run;
            run += g_deg[i];
        }
    }
    if (t == 0) g_rowptr[N] = E;
}

__global__ void scatter_kernel(const int* __restrict__ src, const int* __restrict__ dst,
                               const float* __restrict__ dist, int E) {
    int i = blockIdx.x * blockDim.x + threadIdx.x;
    int e4 = i * 4;
    if (e4 + 3 < E) {
        int4   s = __ldg((const int4*)src + i);
        int4   d = __ldg((const int4*)dst + i);
        float4 v = __ldg((const float4*)dist + i);
        int p;
        p = atomicAdd(&g_cursor[d.x], 1); g_edge_s[p] = make_int2(s.x, __float_as_int(v.x));
        p = atomicAdd(&g_cursor[d.y], 1); g_edge_s[p] = make_int2(s.y, __float_as_int(v.y));
        p = atomicAdd(&g_cursor[d.z], 1); g_edge_s[p] = make_int2(s.z, __float_as_int(v.z));
        p = atomicAdd(&g_cursor[d.w], 1); g_edge_s[p] = make_int2(s.w, __float_as_int(v.w));
    } else {
        for (int e = e4; e < E; e++) {
            int p = atomicAdd(&g_cursor[dst[e]], 1);
            g_edge_s[p] = make_int2(src[e], __float_as_int(dist[e]));
        }
    }
}

// ---------------- filter table build (value+delta interleaved, direct) ----------------
#define TROWS 16
__global__ void table_kernel(const float* __restrict__ Wf1, const float* __restrict__ bf1,
                             const float* __restrict__ Wf2, const float* __restrict__ bf2) {
    extern __shared__ float ts[];
    float* wbuf = ts;
    float* rbfb = ts + H * H;
    float* hidb = rbfb + (TROWS + 1) * H;

    const int chunks = TAB / TROWS;
    int l  = blockIdx.x / chunks;
    int r0 = (blockIdx.x % chunks) * TROWS;
    int j  = threadIdx.x;
    float cj = j * (1.0f / (H - 1));

    #pragma unroll
    for (int r = 0; r <= TROWS; r++) {
        int rr = min(r0 + r, TAB - 1);
        float d = rr * (1.0f / (TAB - 1));
        float u = d - cj;
        rbfb[r * H + j] = expf(-GAMMA_C * u * u);
    }

    const float4* w1 = (const float4*)(Wf1 + (size_t)l * H * H);
    for (int i = j; i < H * H / 4; i += 128) ((float4*)wbuf)[i] = __ldg(w1 + i);
    __syncthreads();

    float b1v = bf1[l * H + j];
    float b2v = bf2[l * H + j];

    #pragma unroll 2
    for (int r = 0; r <= TROWS; r++) {
        float acc = b1v;
        #pragma unroll 8
        for (int i = 0; i < H; i++) acc = fmaf(rbfb[r * H + i], wbuf[i * H + j], acc);
        hidb[r * H + j] = ssp(acc);
    }
    __syncthreads();

    const float4* w2 = (const float4*)(Wf2 + (size_t)l * H * H);
    for (int i = j; i < H * H / 4; i += 128) ((float4*)wbuf)[i] = __ldg(w2 + i);
    __syncthreads();

    __half vh[TROWS + 1];
    #pragma unroll 2
    for (int r = 0; r <= TROWS; r++) {
        float acc = b2v;
        #pragma unroll 8
        for (int i = 0; i < H; i++) acc = fmaf(hidb[r * H + i], wbuf[i * H + j], acc);
        vh[r] = __float2half_rn(acc);
    }

    int grp = j >> 2, w = j & 3;
    #pragma unroll
    for (int r = 0; r < TROWS; r++) {
        __half* dst = g_table2 + ((size_t)l * TAB + r0 + r) * (2 * H);
        dst[grp * 8 + w]     = vh[r];
        dst[grp * 8 + 4 + w] = __hsub(vh[r + 1], vh[r]);
    }
}

// ---------------- GEMM tiling constants ----------------
#define BM 128
#define AS_STRIDE 36
#define BS_STRIDE 132
#define TS_STRIDE 136    // halves (272 B -> ldmatrix conflict-free)

// ---------------- pipelined tf32 GEMM (initial projection only, K=64) ----------------
template <int KDIM>
__global__ void __launch_bounds__(256, 2) gemm_tf32(const float* __restrict__ A,
                                                    const float* __restrict__ B,
                                                    const float* __restrict__ bias,
                                                    __half* __restrict__ C, int M) {
    constexpr int KITERS = KDIM / 32;
    extern __shared__ float smem[];
    float* Bs = smem;
    float* As = smem + KDIM * BS_STRIDE;

    int tid  = threadIdx.x;
    int lane = tid & 31;
    int wid  = tid >> 5;
    int wm   = wid >> 2;
    int wn   = wid & 3;
    int grp  = lane >> 2;
    int thr4 = lane & 3;
    int r0   = blockIdx.x * BM;

    auto stage_A = [&](int chunk, int buf) {
        float* dstbase = As + buf * (BM * AS_STRIDE);
        #pragma unroll
        for (int j = 0; j < 4; j++) {
            int idx = tid + j * 256;
            int row = idx >> 3;
            int k4  = idx & 7;
            int gr  = r0 + row;
            int grc = gr < M ? gr : 0;
            const float* gp = A + (size_t)grc * KDIM + chunk * 32 + k4 * 4;
            unsigned sa = (unsigned)__cvta_generic_to_shared(dstbase + row * AS_STRIDE + k4 * 4);
            cp_async16(sa, gp, (gr < M) ? 16 : 0);
        }
        asm volatile("cp.async.commit_group;");
    };

    stage_A(0, 0);
    if (KITERS > 1) stage_A(1, 1);

    #pragma unroll
    for (int i = tid; i < KDIM * 32; i += 256) {
        int k  = i >> 5;
        int n4 = i & 31;
        float4 v = *(const float4*)(B + (size_t)k * H + n4 * 4);
        float* d = Bs + k * BS_STRIDE + n4 * 4;
        d[0] = __uint_as_float(f2tf32(v.x));
        d[1] = __uint_as_float(f2tf32(v.y));
        d[2] = __uint_as_float(f2tf32(v.z));
        d[3] = __uint_as_float(f2tf32(v.w));
    }

    float c[4][4][4];
    #pragma unroll
    for (int i = 0; i < 4; i++)
        #pragma unroll
        for (int j = 0; j < 4; j++)
            #pragma unroll
            for (int r = 0; r < 4; r++) c[i][j][r] = 0.f;

    #pragma unroll
    for (int ki = 0; ki < KITERS; ki++) {
        if (ki == KITERS - 1) asm volatile("cp.async.wait_group 0;" ::: "memory");
        else                  asm volatile("cp.async.wait_group 1;" ::: "memory");
        __syncthreads();

        const float* Ab = As + (ki & 1) * (BM * AS_STRIDE);
        #pragma unroll
        for (int ks = 0; ks < 4; ks++) {
            unsigned a[4][4];
            #pragma unroll
            for (int am = 0; am < 4; am++) {
                const float* base = Ab + (size_t)(wm * 64 + am * 16 + grp) * AS_STRIDE + ks * 8 + thr4;
                a[am][0] = f2tf32(base[0]);
                a[am][1] = f2tf32(base[8 * AS_STRIDE]);
                a[am][2] = f2tf32(base[4]);
                a[am][3] = f2tf32(base[8 * AS_STRIDE + 4]);
            }
            unsigned b[4][2];
            #pragma unroll
            for (int an = 0; an < 4; an++) {
                const float* bb = Bs + (size_t)(ki * 32 + ks * 8 + thr4) * BS_STRIDE + wn * 32 + an * 8 + grp;
                b[an][0] = __float_as_uint(bb[0]);
                b[an][1] = __float_as_uint(bb[4 * BS_STRIDE]);
            }
            #pragma unroll
            for (int am = 0; am < 4; am++)
                #pragma unroll
                for (int an = 0; an < 4; an++) {
                    asm volatile(
                        "mma.sync.aligned.m16n8k8.row.col.f32.tf32.tf32.f32 "
                        "{%0,%1,%2,%3}, {%4,%5,%6,%7}, {%8,%9}, {%0,%1,%2,%3};"
                        : "+f"(c[am][an][0]), "+f"(c[am][an][1]),
                          "+f"(c[am][an][2]), "+f"(c[am][an][3])
                        : "r"(a[am][0]), "r"(a[am][1]), "r"(a[am][2]), "r"(a[am][3]),
                          "r"(b[an][0]), "r"(b[an][1]));
                }
        }

        if (ki + 2 < KITERS) {
            __syncthreads();
            stage_A(ki + 2, ki & 1);
        }
    }

    #pragma unroll
    for (int an = 0; an < 4; an++) {
        int col = wn * 32 + an * 8 + 2 * thr4;
        float2 bv = *(const float2*)(bias + col);
        #pragma unroll
        for (int am = 0; am < 4; am++) {
            int row0 = r0 + wm * 64 + am * 16 + grp;
            if (row0 < M)
                *(__half2*)(C + (size_t)row0 * H + col) =
                    __floats2half2_rn(c[am][an][0] + bv.x, c[am][an][1] + bv.y);
            if (row0 + 8 < M)
                *(__half2*)(C + (size_t)(row0 + 8) * H + col) =
                    __floats2half2_rn(c[am][an][2] + bv.x, c[am][an][3] + bv.y);
        }
    }
}

// ---------------- fp16 layer GEMM (ldmatrix fragments, pretransposed weights) ----------------
// !LAST: P = relu(A@W2 + b2) @ W1 + b1
//  LAST: pool += relu(A@W2 + b2) per graph (direct red), counts per graph
template <bool LAST>
__global__ void __launch_bounds__(256, 2) layer_gemm(const __half* __restrict__ A,
                                                     const __half* __restrict__ w2t,
                                                     const float* __restrict__ b2,
                                                     const __half* __restrict__ w1t,
                                                     const float* __restrict__ b1,
                                                     __half* __restrict__ P,
                                                     const int* __restrict__ gid, int M) {
    extern __shared__ __half shh[];
    __half* Ah  = shh;
    __half* W2t = shh + 128 * TS_STRIDE;
    __half* W1t = W2t + 128 * TS_STRIDE;

    int tid  = threadIdx.x;
    int lane = tid & 31;
    int wid  = tid >> 5;
    int wm   = wid >> 2;
    int wn   = wid & 3;
    int grp  = lane >> 2;
    int thr4 = lane & 3;
    int r0   = blockIdx.x * BM;

    #pragma unroll
    for (int j = 0; j < 8; j++) {
        int cidx = tid + j * 256;
        int row  = cidx >> 4;
        int c16  = cidx & 15;
        int gr   = r0 + row;
        int grc  = gr < M ? gr : 0;
        cp_async16((unsigned)__cvta_generic_to_shared(Ah + row * TS_STRIDE + c16 * 8),
                   A + (size_t)grc * H + c16 * 8, (gr < M) ? 16 : 0);
    }
    #pragma unroll
    for (int j = 0; j < 8; j++) {
        int cidx = tid + j * 256;
        int row  = cidx >> 4;
        int c16  = cidx & 15;
        cp_async16((unsigned)__cvta_generic_to_shared(W2t + row * TS_STRIDE + c16 * 8),
                   w2t + (size_t)row * H + c16 * 8, 16);
    }
    if constexpr (!LAST) {
        #pragma unroll
        for (int j = 0; j < 8; j++) {
            int cidx = tid + j * 256;
            int row  = cidx >> 4;
            int c16  = cidx & 15;
            cp_async16((unsigned)__cvta_generic_to_shared(W1t + row * TS_STRIDE + c16 * 8),
                       w1t + (size_t)row * H + c16 * 8, 16);
        }
    }
    asm volatile("cp.async.commit_group;");
    asm volatile("cp.async.wait_group 0;" ::: "memory");
    __syncthreads();

    unsigned AhU  = (unsigned)__cvta_generic_to_shared(Ah);
    unsigned W2tU = (unsigned)__cvta_generic_to_shared(W2t);

    int rowA  = lane & 15;
    int colA8 = (lane >> 4) * 8;
    int rowB  = (lane & 7) + ((lane >> 4) & 1) * 8;
    int colB8 = ((lane >> 3) & 1) * 8;

    float c[4][4][4];
    #pragma unroll
    for (int i = 0; i < 4; i++)
        #pragma unroll
        for (int j = 0; j < 4; j++)
            #pragma unroll
            for (int r = 0; r < 4; r++) c[i][j][r] = 0.f;

    #pragma unroll
    for (int kc = 0; kc < 8; kc++) {
        unsigned a[4][4];
        #pragma unroll
        for (int am = 0; am < 4; am++) {
            unsigned addr = AhU + (unsigned)(((wm * 64 + am * 16 + rowA) * TS_STRIDE
                                              + kc * 16 + colA8) * 2);
            ldsm_x4(a[am][0], a[am][1], a[am][2], a[am][3], addr);
        }
        unsigned b[4][2];
        #pragma unroll
        for (int anp = 0; anp < 2; anp++) {
            int n0 = wn * 32 + anp * 16;
            unsigned addr = W2tU + (unsigned)(((n0 + rowB) * TS_STRIDE + kc * 16 + colB8) * 2);
            ldsm_x4(b[2 * anp][0], b[2 * anp][1], b[2 * anp + 1][0], b[2 * anp + 1][1], addr);
        }
        #pragma unroll
        for (int am = 0; am < 4; am++)
            #pragma unroll
            for (int an = 0; an < 4; an++) {
                asm volatile(
                    "mma.sync.aligned.m16n8k16.row.col.f32.f16.f16.f32 "
                    "{%0,%1,%2,%3}, {%4,%5,%6,%7}, {%8,%9}, {%0,%1,%2,%3};"
                    : "+f"(c[am][an][0]), "+f"(c[am][an][1]),
                      "+f"(c[am][an][2]), "+f"(c[am][an][3])
                    : "r"(a[am][0]), "r"(a[am][1]), "r"(a[am][2]), "r"(a[am][3]),
                      "r"(b[an][0]), "r"(b[an][1]));
            }
    }

    if constexpr (LAST) {
        #pragma unroll
        for (int am = 0; am < 4; am++) {
            int row0 = r0 + wm * 64 + am * 16 + grp;
            int g0 = (row0 < M)     ? __ldg(gid + row0)     : 0;
            int g1 = (row0 + 8 < M) ? __ldg(gid + row0 + 8) : 0;
            #pragma unroll
            for (int an = 0; an < 4; an++) {
                int col = wn * 32 + an * 8 + 2 * thr4;
                float2 bv = *(const float2*)(b2 + col);
                float o0x = fmaxf(c[am][an][0] + bv.x, 0.f);
                float o0y = fmaxf(c[am][an][1] + bv.y, 0.f);
                float o1x = fmaxf(c[am][an][2] + bv.x, 0.f);
                float o1y = fmaxf(c[am][an][3] + bv.y, 0.f);
                if (row0 < M) {
                    float* p = g_pool + (size_t)g0 * H + col;
                    asm volatile("red.global.add.v2.f32 [%0], {%1,%2};"
                                 :: "l"(p), "f"(o0x), "f"(o0y) : "memory");
                }
                if (row0 + 8 < M) {
                    float* p = g_pool + (size_t)g1 * H + col;
                    asm volatile("red.global.add.v2.f32 [%0], {%1,%2};"
                                 :: "l"(p), "f"(o1x), "f"(o1y) : "memory");
                }
            }
            if (wn == 0 && thr4 == 0) {
                if (row0 < M)     atomicAdd(&g_cnt[g0], 1.0f);
                if (row0 + 8 < M) atomicAdd(&g_cnt[g1], 1.0f);
            }
        }
        return;
    }

    __syncthreads();

    #pragma unroll
    for (int an = 0; an < 4; an++) {
        int col = wn * 32 + an * 8 + 2 * thr4;
        float2 bv = *(const float2*)(b2 + col);
        #pragma unroll
        for (int am = 0; am < 4; am++) {
            int r = wm * 64 + am * 16 + grp;
            *(__half2*)(Ah + (size_t)r * TS_STRIDE + col) =
                __floats2half2_rn(fmaxf(c[am][an][0] + bv.x, 0.f),
                                  fmaxf(c[am][an][1] + bv.y, 0.f));
            *(__half2*)(Ah + (size_t)(r + 8) * TS_STRIDE + col) =
                __floats2half2_rn(fmaxf(c[am][an][2] + bv.x, 0.f),
                                  fmaxf(c[am][an][3] + bv.y, 0.f));
        }
    }
    __syncthreads();

    unsigned W1tU = (unsigned)__cvta_generic_to_shared(W1t);

    float p[4][4][4];
    #pragma unroll
    for (int i = 0; i < 4; i++)
        #pragma unroll
        for (int j = 0; j < 4; j++)
            #pragma unroll
            for (int r = 0; r < 4; r++) p[i][j][r] = 0.f;

    #pragma unroll
    for (int kc = 0; kc < 8; kc++) {
        unsigned a[4][4];
        #pragma unroll
        for (int am = 0; am < 4; am++) {
            unsigned addr = AhU + (unsigned)(((wm * 64 + am * 16 + rowA) * TS_STRIDE
                                              + kc * 16 + colA8) * 2);
            ldsm_x4(a[am][0], a[am][1], a[am][2], a[am][3], addr);
        }
        unsigned b[4][2];
        #pragma unroll
        for (int anp = 0; anp < 2; anp++) {
            int n0 = wn * 32 + anp * 16;
            unsigned addr = W1tU + (unsigned)(((n0 + rowB) * TS_STRIDE + kc * 16 + colB8) * 2);
            ldsm_x4(b[2 * anp][0], b[2 * anp][1], b[2 * anp + 1][0], b[2 * anp + 1][1], addr);
        }
        #pragma unroll
        for (int am = 0; am < 4; am++)
            #pragma unroll
            for (int an = 0; an < 4; an++) {
                asm volatile(
                    "mma.sync.aligned.m16n8k16.row.col.f32.f16.f16.f32 "
                    "{%0,%1,%2,%3}, {%4,%5,%6,%7}, {%8,%9}, {%0,%1,%2,%3};"
                    : "+f"(p[am][an][0]), "+f"(p[am][an][1]),
                      "+f"(p[am][an][2]), "+f"(p[am][an][3])
                    : "r"(a[am][0]), "r"(a[am][1]), "r"(a[am][2]), "r"(a[am][3]),
                      "r"(b[an][0]), "r"(b[an][1]));
            }
    }

    #pragma unroll
    for (int an = 0; an < 4; an++) {
        int col = wn * 32 + an * 8 + 2 * thr4;
        float2 bv = *(const float2*)(b1 + col);
        #pragma unroll
        for (int am = 0; am < 4; am++) {
            int row0 = r0 + wm * 64 + am * 16 + grp;
            if (row0 < M)
                *(__half2*)(P + (size_t)row0 * H + col) =
                    __floats2half2_rn(p[am][an][0] + bv.x, p[am][an][1] + bv.y);
            if (row0 + 8 < M)
                *(__half2*)(P + (size_t)(row0 + 8) * H + col) =
                    __floats2half2_rn(p[am][an][2] + bv.x, p[am][an][3] + bv.y);
        }
    }
}

// ---------------- CSR aggregation: warp/node, 2-edge ILP, value+delta table ----------------
__global__ void agg_kernel(const __half* __restrict__ table2,
                           const __half* __restrict__ proj,
                           const int*   __restrict__ rowptr,
                           const int2*  __restrict__ edges,
                           __half*      __restrict__ agg, int N) {
    int n = blockIdx.x * 8 + (threadIdx.x >> 5);
    if (n >= N) return;
    int lane = threadIdx.x & 31;

    int beg = __ldg(rowptr + n);
    int end = __ldg(rowptr + n + 1);

    float ax = 0.f, ay = 0.f, az = 0.f, aw = 0.f;

    auto ldidx = [&](int j, int& s, int& k, float& fr) {
        int2 v = __ldg(edges + j);
        s = v.x;
        float d = __int_as_float(v.y);
        float pos = d * (float)(TAB - 1);
        int kk = (int)pos;
        kk = min(max(kk, 0), TAB - 2);
        fr = pos - (float)kk;
        k = kk;
    };

    auto edge_msg = [&](const uint4& q, const uint2& hp, float fr,
                        __half2& m0, __half2& m1) {
        __half2 fr2 = __float2half2_rn(fr);
        __half2 v0 = *(const __half2*)&q.x;
        __half2 v1 = *(const __half2*)&q.y;
        __half2 d0 = *(const __half2*)&q.z;
        __half2 d1 = *(const __half2*)&q.w;
        __half2 pa = *(const __half2*)&hp.x;
        __half2 pb = *(const __half2*)&hp.y;
        m0 = __hmul2(__hfma2(fr2, d0, v0), pa);
        m1 = __hmul2(__hfma2(fr2, d1, v1), pb);
    };

    int sA = 0, kA = 0, sB = 0, kB = 0;
    float frA = 0.f, frB = 0.f;
    if (beg < end)     ldidx(beg,     sA, kA, frA);
    if (beg + 1 < end) ldidx(beg + 1, sB, kB, frB);

    for (int i = beg; i < end; i += 2) {
        bool has2 = (i + 1 < end);
        int sC = 0, kC = 0, sD = 0, kD = 0;
        float frC = 0.f, frD = 0.f;
        if (i + 2 < end) ldidx(i + 2, sC, kC, frC);
        if (i + 3 < end) ldidx(i + 3, sD, kD, frD);

        uint4 qA = __ldg((const uint4*)(table2 + (size_t)kA * (2 * H)) + lane);
        uint2 hpA = __ldg((const uint2*)(proj + (size_t)sA * H) + lane);
        uint4 qB;
        uint2 hpB;
        if (has2) {
            qB  = __ldg((const uint4*)(table2 + (size_t)kB * (2 * H)) + lane);
            hpB = __ldg((const uint2*)(proj + (size_t)sB * H) + lane);
        }

        __half2 mA0, mA1;
        edge_msg(qA, hpA, frA, mA0, mA1);
        if (has2) {
            __half2 mB0, mB1;
            edge_msg(qB, hpB, frB, mB0, mB1);
            mA0 = __hadd2(mA0, mB0);
            mA1 = __hadd2(mA1, mB1);
        }
        float2 f0 = __half22float2(mA0);
        float2 f1 = __half22float2(mA1);
        ax += f0.x; ay += f0.y; az += f1.x; aw += f1.y;

        sA = sC; kA = kC; frA = frC;
        sB = sD; kB = kD; frB = frD;
    }

    uint2 o;
    __half2 h01 = __floats2half2_rn(ax, ay);
    __half2 h23 = __floats2half2_rn(az, aw);
    o.x = *(unsigned*)&h01;
    o.y = *(unsigned*)&h23;
    *(uint2*)(agg + (size_t)n * H + lane * 4) = o;
}

// ---------------- readout: mean, FC, log_softmax ----------------
__global__ void readout_kernel(const float* __restrict__ fcw, const float* __restrict__ fcb,
                               float* __restrict__ out) {
    int g = blockIdx.x;
    int t = threadIdx.x;
    __shared__ float p[H];
    __shared__ float logits[C_OUT];

    float c = fmaxf(g_cnt[g], 1.0f);
    p[t] = g_pool[(size_t)g * H + t] / c;
    __syncthreads();

    if (t < C_OUT) {
        float acc = fcb[t];
        #pragma unroll 8
        for (int h = 0; h < H; h++) acc = fmaf(p[h], fcw[h * C_OUT + t], acc);
        logits[t] = acc;
    }
    __syncthreads();

    if (t == 0) {
        float mx = -1e30f;
        for (int i = 0; i < C_OUT; i++) mx = fmaxf(mx, logits[i]);
        float se = 0.f;
        for (int i = 0; i < C_OUT; i++) se += expf(logits[i] - mx);
        float lse = mx + logf(se);
        for (int i = 0; i < C_OUT; i++) out[g * C_OUT + i] = logits[i] - lse;
    }
}

// ---------------- launch ----------------
extern "C" void kernel_launch(void* const* d_in, const int* in_sizes, int n_in,
                              void* d_out, int out_size) {
    const float* x         = (const float*)d_in[0];
    const float* edge_dist = (const float*)d_in[1];
    const int*   esrc      = (const int*)  d_in[2];
    const int*   edst      = (const int*)  d_in[3];
    const int*   gid       = (const int*)  d_in[4];
    const float* W1_0      = (const float*)d_in[5];
    const float* b1_0      = (const float*)d_in[6];
    const float* W1_rest   = (const float*)d_in[7];
    const float* b1_rest   = (const float*)d_in[8];
    const float* Wf1       = (const float*)d_in[9];
    const float* bf1       = (const float*)d_in[10];
    const float* Wf2       = (const float*)d_in[11];
    const float* bf2       = (const float*)d_in[12];
    const float* W2        = (const float*)d_in[13];
    const float* b2        = (const float*)d_in[14];
    const float* fcw       = (const float*)d_in[15];
    const float* fcb       = (const float*)d_in[16];
    float* out = (float*)d_out;

    int E = in_sizes[1];
    int N = in_sizes[4];

    __half *proj, *agg, *table2, *w2t, *w1t;
    int *rowptr, *deg;
    int2 *edges;
    cudaGetSymbolAddress((void**)&proj,   g_proj);
    cudaGetSymbolAddress((void**)&agg,    g_agg);
    cudaGetSymbolAddress((void**)&table2, g_table2);
    cudaGetSymbolAddress((void**)&rowptr, g_rowptr);
    cudaGetSymbolAddress((void**)&deg,    g_deg);
    cudaGetSymbolAddress((void**)&edges,  g_edge_s);
    cudaGetSymbolAddress((void**)&w2t,    g_w2t);
    cudaGetSymbolAddress((void**)&w1t,    g_w1t);

    const int smem64   = (64 * BS_STRIDE + 2 * BM * AS_STRIDE) * 4;
    const int smemL    = 3 * 128 * TS_STRIDE * 2;
    const int smemLast = 2 * 128 * TS_STRIDE * 2;
    const int smemTab  = (H * H + 2 * (TROWS + 1) * H) * 4;
    cudaFuncSetAttribute(gemm_tf32<F_IN>,
                         cudaFuncAttributeMaxDynamicSharedMemorySize, smem64);
    cudaFuncSetAttribute(layer_gemm<false>,
                         cudaFuncAttributeMaxDynamicSharedMemorySize, smemL);
    cudaFuncSetAttribute(layer_gemm<true>,
                         cudaFuncAttributeMaxDynamicSharedMemorySize, smemLast);
    cudaFuncSetAttribute(table_kernel,
                         cudaFuncAttributeMaxDynamicSharedMemorySize, smemTab);

    // precompute: tables (value+delta, direct), transposed weights (+pool zero)
    table_kernel<<<L_LAYERS * (TAB / TROWS), H, smemTab>>>(Wf1, bf1, Wf2, bf2);
    wtrans_kernel<<<dim3(64, L_LAYERS), 256>>>(W2, W1_rest);

    // build CSR by dst (memset + count + 1-block scan + scatter)
    cudaMemsetAsync(deg, 0, (size_t)N * sizeof(int));
    deg_count_kernel<<<(E / 4 + 256) / 256, 256>>>(edst, E);
    scan_kernel<<<1, 1024>>>(N, E);
    scatter_kernel<<<(E / 4 + 256) / 256, 256>>>(esrc, edst, edge_dist, E);

    int gemm_blocks = (N + BM - 1) / BM;
    int agg_blocks  = (N + 7) / 8;

    // initial projection: proj = x @ W1_0 + b1_0 (fp16 out)
    gemm_tf32<F_IN><<<gemm_blocks, 256, smem64>>>(x, W1_0, b1_0, proj, N);

    for (int l = 0; l < L_LAYERS; l++) {
        agg_kernel<<<agg_blocks, 256>>>(table2 + (size_t)l * TAB * 2 * H,
                                        proj, rowptr, edges, agg, N);

        if (l < L_LAYERS - 1) {
            layer_gemm<false><<<gemm_blocks, 256, smemL>>>(
                agg,
                w2t + (size_t)l * H * H, b2 + (size_t)l * H,
                w1t + (size_t)l * H * H, b1_rest + (size_t)l * H,
                proj, nullptr, N);
        } else {
            layer_gemm<true><<<gemm_blocks, 256, smemLast>>>(
                agg, w2t + (size_t)l * H * H, b2 + (size_t)l * H,
                nullptr, nullptr, nullptr, gid, N);
        }
    }

    // FC + log_softmax
    readout_kernel<<<G_GRAPHS, H>>>(fcw, fcb, out);
}

// round 16
// speedup vs baseline: 1.2044x; 1.2044x over previous
#include <cuda_runtime.h>
#include <cuda_fp16.h>

// Problem constants (fixed by the reference)
#define N_NODES 50000
#define N_EDGES 800000
#define F_IN    64
#define H       128
#define L_LAYERS 4
#define G_GRAPHS 64
#define C_OUT   10
#define TAB     256           // filter table: L1-resident
#define GAMMA_C 10.0f

// ---------------- scratch (device globals: allocation-free) ----------------
__device__ __half g_proj[N_NODES * H];
__device__ __half g_agg [N_NODES * H];
__device__ __half g_table2[L_LAYERS * TAB * 2 * H];   // interleaved (4 val, 4 delta) groups
__device__ __half g_w2t[L_LAYERS * H * H];
__device__ __half g_w1t[(L_LAYERS - 1) * H * H];
__device__ float  g_pool[G_GRAPHS * H];
__device__ float  g_cnt [G_GRAPHS];
// CSR-by-dst scratch
__device__ int    g_deg   [N_NODES];
__device__ int    g_rowptr[N_NODES + 1];
__device__ int    g_cursor[N_NODES];
__device__ int    g_bsum  [64];
__device__ int    g_boff  [64];
__device__ int2   g_edge_s[N_EDGES];

// ---------------- small helpers ----------------
__device__ __forceinline__ float ssp(float v) {
    return fmaxf(v, 0.f) + log1pf(expf(-fabsf(v))) - 0.6931472f;
}

__device__ __forceinline__ unsigned f2tf32(float x) {
    unsigned u;
    asm("cvt.rna.tf32.f32 %0, %1;" : "=r"(u) : "f"(x));
    return u;
}

__device__ __forceinline__ void cp_async16(unsigned saddr, const void* gaddr, int szbytes) {
    asm volatile("cp.async.cg.shared.global [%0], [%1], 16, %2;"
                 :: "r"(saddr), "l"(gaddr), "r"(szbytes));
}

__device__ __forceinline__ void ldsm_x4(unsigned& r0, unsigned& r1, unsigned& r2, unsigned& r3,
                                        unsigned addr) {
    asm volatile("ldmatrix.sync.aligned.m8n8.x4.shared.b16 {%0,%1,%2,%3}, [%4];"
                 : "=r"(r0), "=r"(r1), "=r"(r2), "=r"(r3) : "r"(addr));
}

// ---------------- weight pre-transpose (fp16 [n][k]) + pool zeroing ----------------
__global__ void wtrans_kernel(const float* __restrict__ W2, const float* __restrict__ W1_rest) {
    int l = blockIdx.y;
    int i = blockIdx.x * 256 + threadIdx.x;   // 0..16383
    int k = i >> 7, n = i & 127;
    g_w2t[l * H * H + n * H + k] = __float2half_rn(W2[l * H * H + k * H + n]);
    if (l < L_LAYERS - 1)
        g_w1t[l * H * H + n * H + k] = __float2half_rn(W1_rest[l * H * H + k * H + n]);
    if (l == 0) {
        if (i < G_GRAPHS * H) g_pool[i] = 0.f;
        if (i < G_GRAPHS)     g_cnt[i]  = 0.f;
    }
}

// ---------------- CSR build ----------------
__global__ void deg_count_kernel(const int* __restrict__ dst, int E) {
    int i = blockIdx.x * blockDim.x + threadIdx.x;
    int e4 = i * 4;
    if (e4 + 3 < E) {
        int4 d = __ldg((const int4*)dst + i);
        atomicAdd(&g_deg[d.x], 1);
        atomicAdd(&g_deg[d.y], 1);
        atomicAdd(&g_deg[d.z], 1);
        atomicAdd(&g_deg[d.w], 1);
    } else {
        for (int e = e4; e < E; e++) atomicAdd(&g_deg[dst[e]], 1);
    }
}

__global__ void scan_bsum_kernel(int N) {
    __shared__ int ws[32];
    int t = threadIdx.x;
    int lane = t & 31, w = t >> 5;
    int i = blockIdx.x * 1024 + t;
    int v = (i < N) ? g_deg[i] : 0;
    #pragma unroll
    for (int o = 16; o > 0; o >>= 1) v += __shfl_down_sync(0xffffffffu, v, o);
    if (lane == 0) ws[w] = v;
    __syncthreads();
    if (w == 0) {
        int s = ws[lane];
        #pragma unroll
        for (int o = 16; o > 0; o >>= 1) s += __shfl_down_sync(0xffffffffu, s, o);
        if (lane == 0) g_bsum[blockIdx.x] = s;
    }
}

__global__ void scan_boff_kernel(int nb, int E) {
    __shared__ int sh[64];
    int t = threadIdx.x;
    int v = (t < nb) ? g_bsum[t] : 0;
    sh[t] = v;
    __syncthreads();
    #pragma unroll
    for (int ofs = 1; ofs < 64; ofs <<= 1) {
        int x = (t >= ofs) ? sh[t - ofs] : 0;
        __syncthreads();
        sh[t] += x;
        __syncthreads();
    }
    if (t < nb) g_boff[t] = sh[t] - v;
    if (t == 0) g_rowptr[N_NODES] = E;
}

__global__ void scan_final_kernel(int N) {
    __shared__ int ws[32];
    int t = threadIdx.x;
    int lane = t & 31, w = t >> 5;
    int i = blockIdx.x * 1024 + t;
    int v = (i < N) ? g_deg[i] : 0;
    int x = v;
    #pragma unroll
    for (int o = 1; o < 32; o <<= 1) {
        int y = __shfl_up_sync(0xffffffffu, x, o);
        if (lane >= o) x += y;
    }
    if (lane == 31) ws[w] = x;
    __syncthreads();
    if (w == 0) {
        int s = ws[lane];
        #pragma unroll
        for (int o = 1; o < 32; o <<= 1) {
            int y = __shfl_up_sync(0xffffffffu, s, o);
            if (lane >= o) s += y;
        }
        ws[lane] = s;
    }
    __syncthreads();
    int warpExcl = (w == 0) ? 0 : ws[w - 1];
    if (i < N) {
        int ex = x - v + warpExcl + g_boff[blockIdx.x];
        g_rowptr[i] = ex;
        g_cursor[i] = ex;
    }
}

__global__ void scatter_kernel(const int* __restrict__ src, const int* __restrict__ dst,
                               const float* __restrict__ dist, int E) {
    int i = blockIdx.x * blockDim.x + threadIdx.x;
    int e4 = i * 4;
    if (e4 + 3 < E) {
        int4   s = __ldg((const int4*)src + i);
        int4   d = __ldg((const int4*)dst + i);
        float4 v = __ldg((const float4*)dist + i);
        int p;
        p = atomicAdd(&g_cursor[d.x], 1); g_edge_s[p] = make_int2(s.x, __float_as_int(v.x));
        p = atomicAdd(&g_cursor[d.y], 1); g_edge_s[p] = make_int2(s.y, __float_as_int(v.y));
        p = atomicAdd(&g_cursor[d.z], 1); g_edge_s[p] = make_int2(s.z, __float_as_int(v.z));
        p = atomicAdd(&g_cursor[d.w], 1); g_edge_s[p] = make_int2(s.w, __float_as_int(v.w));
    } else {
        for (int e = e4; e < E; e++) {
            int p = atomicAdd(&g_cursor[dst[e]], 1);
            g_edge_s[p] = make_int2(src[e], __float_as_int(dist[e]));
        }
    }
}

// ---------------- filter table build (value+delta interleaved, direct) ----------------
#define TROWS 16
__global__ void table_kernel(const float* __restrict__ Wf1, const float* __restrict__ bf1,
                             const float* __restrict__ Wf2, const float* __restrict__ bf2) {
    extern __shared__ float ts[];
    float* wbuf = ts;
    float* rbfb = ts + H * H;
    float* hidb = rbfb + (TROWS + 1) * H;

    const int chunks = TAB / TROWS;
    int l  = blockIdx.x / chunks;
    int r0 = (blockIdx.x % chunks) * TROWS;
    int j  = threadIdx.x;
    float cj = j * (1.0f / (H - 1));

    #pragma unroll
    for (int r = 0; r <= TROWS; r++) {
        int rr = min(r0 + r, TAB - 1);
        float d = rr * (1.0f / (TAB - 1));
        float u = d - cj;
        rbfb[r * H + j] = expf(-GAMMA_C * u * u);
    }

    const float4* w1 = (const float4*)(Wf1 + (size_t)l * H * H);
    for (int i = j; i < H * H / 4; i += 128) ((float4*)wbuf)[i] = __ldg(w1 + i);
    __syncthreads();

    float b1v = bf1[l * H + j];
    float b2v = bf2[l * H + j];

    #pragma unroll 2
    for (int r = 0; r <= TROWS; r++) {
        float acc = b1v;
        #pragma unroll 8
        for (int i = 0; i < H; i++) acc = fmaf(rbfb[r * H + i], wbuf[i * H + j], acc);
        hidb[r * H + j] = ssp(acc);
    }
    __syncthreads();

    const float4* w2 = (const float4*)(Wf2 + (size_t)l * H * H);
    for (int i = j; i < H * H / 4; i += 128) ((float4*)wbuf)[i] = __ldg(w2 + i);
    __syncthreads();

    __half vh[TROWS + 1];
    #pragma unroll 2
    for (int r = 0; r <= TROWS; r++) {
        float acc = b2v;
        #pragma unroll 8
        for (int i = 0; i < H; i++) acc = fmaf(hidb[r * H + i], wbuf[i * H + j], acc);
        vh[r] = __float2half_rn(acc);
    }

    int grp = j >> 2, w = j & 3;
    #pragma unroll
    for (int r = 0; r < TROWS; r++) {
        __half* dst = g_table2 + ((size_t)l * TAB + r0 + r) * (2 * H);
        dst[grp * 8 + w]     = vh[r];
        dst[grp * 8 + 4 + w] = __hsub(vh[r + 1], vh[r]);
    }
}

// ---------------- GEMM tiling constants ----------------
#define BM 128
#define AS_STRIDE 36
#define BS_STRIDE 132
#define TS_STRIDE 136    // halves (272 B -> ldmatrix conflict-free)

// ---------------- pipelined tf32 GEMM (initial projection only, K=64) ----------------
template <int KDIM>
__global__ void __launch_bounds__(256, 2) gemm_tf32(const float* __restrict__ A,
                                                    const float* __restrict__ B,
                                                    const float* __restrict__ bias,
                                                    __half* __restrict__ C, int M) {
    constexpr int KITERS = KDIM / 32;
    extern __shared__ float smem[];
    float* Bs = smem;
    float* As = smem + KDIM * BS_STRIDE;

    int tid  = threadIdx.x;
    int lane = tid & 31;
    int wid  = tid >> 5;
    int wm   = wid >> 2;
    int wn   = wid & 3;
    int grp  = lane >> 2;
    int thr4 = lane & 3;
    int r0   = blockIdx.x * BM;

    auto stage_A = [&](int chunk, int buf) {
        float* dstbase = As + buf * (BM * AS_STRIDE);
        #pragma unroll
        for (int j = 0; j < 4; j++) {
            int idx = tid + j * 256;
            int row = idx >> 3;
            int k4  = idx & 7;
            int gr  = r0 + row;
            int grc = gr < M ? gr : 0;
            const float* gp = A + (size_t)grc * KDIM + chunk * 32 + k4 * 4;
            unsigned sa = (unsigned)__cvta_generic_to_shared(dstbase + row * AS_STRIDE + k4 * 4);
            cp_async16(sa, gp, (gr < M) ? 16 : 0);
        }
        asm volatile("cp.async.commit_group;");
    };

    stage_A(0, 0);
    if (KITERS > 1) stage_A(1, 1);

    #pragma unroll
    for (int i = tid; i < KDIM * 32; i += 256) {
        int k  = i >> 5;
        int n4 = i & 31;
        float4 v = *(const float4*)(B + (size_t)k * H + n4 * 4);
        float* d = Bs + k * BS_STRIDE + n4 * 4;
        d[0] = __uint_as_float(f2tf32(v.x));
        d[1] = __uint_as_float(f2tf32(v.y));
        d[2] = __uint_as_float(f2tf32(v.z));
        d[3] = __uint_as_float(f2tf32(v.w));
    }

    float c[4][4][4];
    #pragma unroll
    for (int i = 0; i < 4; i++)
        #pragma unroll
        for (int j = 0; j < 4; j++)
            #pragma unroll
            for (int r = 0; r < 4; r++) c[i][j][r] = 0.f;

    #pragma unroll
    for (int ki = 0; ki < KITERS; ki++) {
        if (ki == KITERS - 1) asm volatile("cp.async.wait_group 0;" ::: "memory");
        else                  asm volatile("cp.async.wait_group 1;" ::: "memory");
        __syncthreads();

        const float* Ab = As + (ki & 1) * (BM * AS_STRIDE);
        #pragma unroll
        for (int ks = 0; ks < 4; ks++) {
            unsigned a[4][4];
            #pragma unroll
            for (int am = 0; am < 4; am++) {
                const float* base = Ab + (size_t)(wm * 64 + am * 16 + grp) * AS_STRIDE + ks * 8 + thr4;
                a[am][0] = f2tf32(base[0]);
                a[am][1] = f2tf32(base[8 * AS_STRIDE]);
                a[am][2] = f2tf32(base[4]);
                a[am][3] = f2tf32(base[8 * AS_STRIDE + 4]);
            }
            unsigned b[4][2];
            #pragma unroll
            for (int an = 0; an < 4; an++) {
                const float* bb = Bs + (size_t)(ki * 32 + ks * 8 + thr4) * BS_STRIDE + wn * 32 + an * 8 + grp;
                b[an][0] = __float_as_uint(bb[0]);
                b[an][1] = __float_as_uint(bb[4 * BS_STRIDE]);
            }
            #pragma unroll
            for (int am = 0; am < 4; am++)
                #pragma unroll
                for (int an = 0; an < 4; an++) {
                    asm volatile(
                        "mma.sync.aligned.m16n8k8.row.col.f32.tf32.tf32.f32 "
                        "{%0,%1,%2,%3}, {%4,%5,%6,%7}, {%8,%9}, {%0,%1,%2,%3};"
                        : "+f"(c[am][an][0]), "+f"(c[am][an][1]),
                          "+f"(c[am][an][2]), "+f"(c[am][an][3])
                        : "r"(a[am][0]), "r"(a[am][1]), "r"(a[am][2]), "r"(a[am][3]),
                          "r"(b[an][0]), "r"(b[an][1]));
                }
        }

        if (ki + 2 < KITERS) {
            __syncthreads();
            stage_A(ki + 2, ki & 1);
        }
    }

    #pragma unroll
    for (int an = 0; an < 4; an++) {
        int col = wn * 32 + an * 8 + 2 * thr4;
        float2 bv = *(const float2*)(bias + col);
        #pragma unroll
        for (int am = 0; am < 4; am++) {
            int row0 = r0 + wm * 64 + am * 16 + grp;
            if (row0 < M)
                *(__half2*)(C + (size_t)row0 * H + col) =
                    __floats2half2_rn(c[am][an][0] + bv.x, c[am][an][1] + bv.y);
            if (row0 + 8 < M)
                *(__half2*)(C + (size_t)(row0 + 8) * H + col) =
                    __floats2half2_rn(c[am][an][2] + bv.x, c[am][an][3] + bv.y);
        }
    }
}

// ---------------- fp16 layer GEMM (ldmatrix fragments, pretransposed weights) ----------------
// !LAST: P = relu(A@W2 + b2) @ W1 + b1
//  LAST: pool += relu(A@W2 + b2) per graph (direct red), counts per graph
template <bool LAST>
__global__ void __launch_bounds__(256, 2) layer_gemm(const __half* __restrict__ A,
                                                     const __half* __restrict__ w2t,
                                                     const float* __restrict__ b2,
                                                     const __half* __restrict__ w1t,
                                                     const float* __restrict__ b1,
                                                     __half* __restrict__ P,
                                                     const int* __restrict__ gid, int M) {
    extern __shared__ __half shh[];
    __half* Ah  = shh;
    __half* W2t = shh + 128 * TS_STRIDE;
    __half* W1t = W2t + 128 * TS_STRIDE;

    int tid  = threadIdx.x;
    int lane = tid & 31;
    int wid  = tid >> 5;
    int wm   = wid >> 2;
    int wn   = wid & 3;
    int grp  = lane >> 2;
    int thr4 = lane & 3;
    int r0   = blockIdx.x * BM;

    #pragma unroll
    for (int j = 0; j < 8; j++) {
        int cidx = tid + j * 256;
        int row  = cidx >> 4;
        int c16  = cidx & 15;
        int gr   = r0 + row;
        int grc  = gr < M ? gr : 0;
        cp_async16((unsigned)__cvta_generic_to_shared(Ah + row * TS_STRIDE + c16 * 8),
                   A + (size_t)grc * H + c16 * 8, (gr < M) ? 16 : 0);
    }
    #pragma unroll
    for (int j = 0; j < 8; j++) {
        int cidx = tid + j * 256;
        int row  = cidx >> 4;
        int c16  = cidx & 15;
        cp_async16((unsigned)__cvta_generic_to_shared(W2t + row * TS_STRIDE + c16 * 8),
                   w2t + (size_t)row * H + c16 * 8, 16);
    }
    if constexpr (!LAST) {
        #pragma unroll
        for (int j = 0; j < 8; j++) {
            int cidx = tid + j * 256;
            int row  = cidx >> 4;
            int c16  = cidx & 15;
            cp_async16((unsigned)__cvta_generic_to_shared(W1t + row * TS_STRIDE + c16 * 8),
                       w1t + (size_t)row * H + c16 * 8, 16);
        }
    }
    asm volatile("cp.async.commit_group;");
    asm volatile("cp.async.wait_group 0;" ::: "memory");
    __syncthreads();

    unsigned AhU  = (unsigned)__cvta_generic_to_shared(Ah);
    unsigned W2tU = (unsigned)__cvta_generic_to_shared(W2t);

    int rowA  = lane & 15;
    int colA8 = (lane >> 4) * 8;
    int rowB  = (lane & 7) + ((lane >> 4) & 1) * 8;
    int colB8 = ((lane >> 3) & 1) * 8;

    float c[4][4][4];
    #pragma unroll
    for (int i = 0; i < 4; i++)
        #pragma unroll
        for (int j = 0; j < 4; j++)
            #pragma unroll
            for (int r = 0; r < 4; r++) c[i][j][r] = 0.f;

    #pragma unroll
    for (int kc = 0; kc < 8; kc++) {
        unsigned a[4][4];
        #pragma unroll
        for (int am = 0; am < 4; am++) {
            unsigned addr = AhU + (unsigned)(((wm * 64 + am * 16 + rowA) * TS_STRIDE
                                              + kc * 16 + colA8) * 2);
            ldsm_x4(a[am][0], a[am][1], a[am][2], a[am][3], addr);
        }
        unsigned b[4][2];
        #pragma unroll
        for (int anp = 0; anp < 2; anp++) {
            int n0 = wn * 32 + anp * 16;
            unsigned addr = W2tU + (unsigned)(((n0 + rowB) * TS_STRIDE + kc * 16 + colB8) * 2);
            ldsm_x4(b[2 * anp][0], b[2 * anp][1], b[2 * anp + 1][0], b[2 * anp + 1][1], addr);
        }
        #pragma unroll
        for (int am = 0; am < 4; am++)
            #pragma unroll
            for (int an = 0; an < 4; an++) {
                asm volatile(
                    "mma.sync.aligned.m16n8k16.row.col.f32.f16.f16.f32 "
                    "{%0,%1,%2,%3}, {%4,%5,%6,%7}, {%8,%9}, {%0,%1,%2,%3};"
                    : "+f"(c[am][an][0]), "+f"(c[am][an][1]),
                      "+f"(c[am][an][2]), "+f"(c[am][an][3])
                    : "r"(a[am][0]), "r"(a[am][1]), "r"(a[am][2]), "r"(a[am][3]),
                      "r"(b[an][0]), "r"(b[an][1]));
            }
    }

    if constexpr (LAST) {
        #pragma unroll
        for (int am = 0; am < 4; am++) {
            int row0 = r0 + wm * 64 + am * 16 + grp;
            int g0 = (row0 < M)     ? __ldg(gid + row0)     : 0;
            int g1 = (row0 + 8 < M) ? __ldg(gid + row0 + 8) : 0;
            #pragma unroll
            for (int an = 0; an < 4; an++) {
                int col = wn * 32 + an * 8 + 2 * thr4;
                float2 bv = *(const float2*)(b2 + col);
                float o0x = fmaxf(c[am][an][0] + bv.x, 0.f);
                float o0y = fmaxf(c[am][an][1] + bv.y, 0.f);
                float o1x = fmaxf(c[am][an][2] + bv.x, 0.f);
                float o1y = fmaxf(c[am][an][3] + bv.y, 0.f);
                if (row0 < M) {
                    float* p = g_pool + (size_t)g0 * H + col;
                    asm volatile("red.global.add.v2.f32 [%0], {%1,%2};"
                                 :: "l"(p), "f"(o0x), "f"(o0y) : "memory");
                }
                if (row0 + 8 < M) {
                    float* p = g_pool + (size_t)g1 * H + col;
                    asm volatile("red.global.add.v2.f32 [%0], {%1,%2};"
                                 :: "l"(p), "f"(o1x), "f"(o1y) : "memory");
                }
            }
            if (wn == 0 && thr4 == 0) {
                if (row0 < M)     atomicAdd(&g_cnt[g0], 1.0f);
                if (row0 + 8 < M) atomicAdd(&g_cnt[g1], 1.0f);
            }
        }
        return;
    }

    __syncthreads();

    #pragma unroll
    for (int an = 0; an < 4; an++) {
        int col = wn * 32 + an * 8 + 2 * thr4;
        float2 bv = *(const float2*)(b2 + col);
        #pragma unroll
        for (int am = 0; am < 4; am++) {
            int r = wm * 64 + am * 16 + grp;
            *(__half2*)(Ah + (size_t)r * TS_STRIDE + col) =
                __floats2half2_rn(fmaxf(c[am][an][0] + bv.x, 0.f),
                                  fmaxf(c[am][an][1] + bv.y, 0.f));
            *(__half2*)(Ah + (size_t)(r + 8) * TS_STRIDE + col) =
                __floats2half2_rn(fmaxf(c[am][an][2] + bv.x, 0.f),
                                  fmaxf(c[am][an][3] + bv.y, 0.f));
        }
    }
    __syncthreads();

    unsigned W1tU = (unsigned)__cvta_generic_to_shared(W1t);

    float p[4][4][4];
    #pragma unroll
    for (int i = 0; i < 4; i++)
        #pragma unroll
        for (int j = 0; j < 4; j++)
            #pragma unroll
            for (int r = 0; r < 4; r++) p[i][j][r] = 0.f;

    #pragma unroll
    for (int kc = 0; kc < 8; kc++) {
        unsigned a[4][4];
        #pragma unroll
        for (int am = 0; am < 4; am++) {
            unsigned addr = AhU + (unsigned)(((wm * 64 + am * 16 + rowA) * TS_STRIDE
                                              + kc * 16 + colA8) * 2);
            ldsm_x4(a[am][0], a[am][1], a[am][2], a[am][3], addr);
        }
        unsigned b[4][2];
        #pragma unroll
        for (int anp = 0; anp < 2; anp++) {
            int n0 = wn * 32 + anp * 16;
            unsigned addr = W1tU + (unsigned)(((n0 + rowB) * TS_STRIDE + kc * 16 + colB8) * 2);
            ldsm_x4(b[2 * anp][0], b[2 * anp][1], b[2 * anp + 1][0], b[2 * anp + 1][1], addr);
        }
        #pragma unroll
        for (int am = 0; am < 4; am++)
            #pragma unroll
            for (int an = 0; an < 4; an++) {
                asm volatile(
                    "mma.sync.aligned.m16n8k16.row.col.f32.f16.f16.f32 "
                    "{%0,%1,%2,%3}, {%4,%5,%6,%7}, {%8,%9}, {%0,%1,%2,%3};"
                    : "+f"(p[am][an][0]), "+f"(p[am][an][1]),
                      "+f"(p[am][an][2]), "+f"(p[am][an][3])
                    : "r"(a[am][0]), "r"(a[am][1]), "r"(a[am][2]), "r"(a[am][3]),
                      "r"(b[an][0]), "r"(b[an][1]));
            }
    }

    #pragma unroll
    for (int an = 0; an < 4; an++) {
        int col = wn * 32 + an * 8 + 2 * thr4;
        float2 bv = *(const float2*)(b1 + col);
        #pragma unroll
        for (int am = 0; am < 4; am++) {
            int row0 = r0 + wm * 64 + am * 16 + grp;
            if (row0 < M)
                *(__half2*)(P + (size_t)row0 * H + col) =
                    __floats2half2_rn(p[am][an][0] + bv.x, p[am][an][1] + bv.y);
            if (row0 + 8 < M)
                *(__half2*)(P + (size_t)(row0 + 8) * H + col) =
                    __floats2half2_rn(p[am][an][2] + bv.x, p[am][an][3] + bv.y);
        }
    }
}

// ---------------- CSR aggregation: warp/node, 2-edge ILP, value+delta table ----------------
__global__ void agg_kernel(const __half* __restrict__ table2,
                           const __half* __restrict__ proj,
                           const int*   __restrict__ rowptr,
                           const int2*  __restrict__ edges,
                           __half*      __restrict__ agg, int N) {
    int n = blockIdx.x * 8 + (threadIdx.x >> 5);
    if (n >= N) return;
    int lane = threadIdx.x & 31;

    int beg = __ldg(rowptr + n);
    int end = __ldg(rowptr + n + 1);

    float ax = 0.f, ay = 0.f, az = 0.f, aw = 0.f;

    auto ldidx = [&](int j, int& s, int& k, float& fr) {
        int2 v = __ldg(edges + j);
        s = v.x;
        float d = __int_as_float(v.y);
        float pos = d * (float)(TAB - 1);
        int kk = (int)pos;
        kk = min(max(kk, 0), TAB - 2);
        fr = pos - (float)kk;
        k = kk;
    };

    auto edge_msg = [&](const uint4& q, const uint2& hp, float fr,
                        __half2& m0, __half2& m1) {
        __half2 fr2 = __float2half2_rn(fr);
        __half2 v0 = *(const __half2*)&q.x;
        __half2 v1 = *(const __half2*)&q.y;
        __half2 d0 = *(const __half2*)&q.z;
        __half2 d1 = *(const __half2*)&q.w;
        __half2 pa = *(const __half2*)&hp.x;
        __half2 pb = *(const __half2*)&hp.y;
        m0 = __hmul2(__hfma2(fr2, d0, v0), pa);
        m1 = __hmul2(__hfma2(fr2, d1, v1), pb);
    };

    int sA = 0, kA = 0, sB = 0, kB = 0;
    float frA = 0.f, frB = 0.f;
    if (beg < end)     ldidx(beg,     sA, kA, frA);
    if (beg + 1 < end) ldidx(beg + 1, sB, kB, frB);

    for (int i = beg; i < end; i += 2) {
        bool has2 = (i + 1 < end);
        int sC = 0, kC = 0, sD = 0, kD = 0;
        float frC = 0.f, frD = 0.f;
        if (i + 2 < end) ldidx(i + 2, sC, kC, frC);
        if (i + 3 < end) ldidx(i + 3, sD, kD, frD);

        uint4 qA = __ldg((const uint4*)(table2 + (size_t)kA * (2 * H)) + lane);
        uint2 hpA = __ldg((const uint2*)(proj + (size_t)sA * H) + lane);
        uint4 qB;
        uint2 hpB;
        if (has2) {
            qB  = __ldg((const uint4*)(table2 + (size_t)kB * (2 * H)) + lane);
            hpB = __ldg((const uint2*)(proj + (size_t)sB * H) + lane);
        }

        __half2 mA0, mA1;
        edge_msg(qA, hpA, frA, mA0, mA1);
        if (has2) {
            __half2 mB0, mB1;
            edge_msg(qB, hpB, frB, mB0, mB1);
            mA0 = __hadd2(mA0, mB0);
            mA1 = __hadd2(mA1, mB1);
        }
        float2 f0 = __half22float2(mA0);
        float2 f1 = __half22float2(mA1);
        ax += f0.x; ay += f0.y; az += f1.x; aw += f1.y;

        sA = sC; kA = kC; frA = frC;
        sB = sD; kB = kD; frB = frD;
    }

    uint2 o;
    __half2 h01 = __floats2half2_rn(ax, ay);
    __half2 h23 = __floats2half2_rn(az, aw);
    o.x = *(unsigned*)&h01;
    o.y = *(unsigned*)&h23;
    *(uint2*)(agg + (size_t)n * H + lane * 4) = o;
}

// ---------------- readout: mean, FC, log_softmax ----------------
__global__ void readout_kernel(const float* __restrict__ fcw, const float* __restrict__ fcb,
                               float* __restrict__ out) {
    int g = blockIdx.x;
    int t = threadIdx.x;
    __shared__ float p[H];
    __shared__ float logits[C_OUT];

    float c = fmaxf(g_cnt[g], 1.0f);
    p[t] = g_pool[(size_t)g * H + t] / c;
    __syncthreads();

    if (t < C_OUT) {
        float acc = fcb[t];
        #pragma unroll 8
        for (int h = 0; h < H; h++) acc = fmaf(p[h], fcw[h * C_OUT + t], acc);
        logits[t] = acc;
    }
    __syncthreads();

    if (t == 0) {
        float mx = -1e30f;
        for (int i = 0; i < C_OUT; i++) mx = fmaxf(mx, logits[i]);
        float se = 0.f;
        for (int i = 0; i < C_OUT; i++) se += expf(logits[i] - mx);
        float lse = mx + logf(se);
        for (int i = 0; i < C_OUT; i++) out[g * C_OUT + i] = logits[i] - lse;
    }
}

// ---------------- launch ----------------
extern "C" void kernel_launch(void* const* d_in, const int* in_sizes, int n_in,
                              void* d_out, int out_size) {
    const float* x         = (const float*)d_in[0];
    const float* edge_dist = (const float*)d_in[1];
    const int*   esrc      = (const int*)  d_in[2];
    const int*   edst      = (const int*)  d_in[3];
    const int*   gid       = (const int*)  d_in[4];
    const float* W1_0      = (const float*)d_in[5];
    const float* b1_0      = (const float*)d_in[6];
    const float* W1_rest   = (const float*)d_in[7];
    const float* b1_rest   = (const float*)d_in[8];
    const float* Wf1       = (const float*)d_in[9];
    const float* bf1       = (const float*)d_in[10];
    const float* Wf2       = (const float*)d_in[11];
    const float* bf2       = (const float*)d_in[12];
    const float* W2        = (const float*)d_in[13];
    const float* b2        = (const float*)d_in[14];
    const float* fcw       = (const float*)d_in[15];
    const float* fcb       = (const float*)d_in[16];
    float* out = (float*)d_out;

    int E = in_sizes[1];
    int N = in_sizes[4];

    __half *proj, *agg, *table2, *w2t, *w1t;
    int *rowptr, *deg;
    int2 *edges;
    cudaGetSymbolAddress((void**)&proj,   g_proj);
    cudaGetSymbolAddress((void**)&agg,    g_agg);
    cudaGetSymbolAddress((void**)&table2, g_table2);
    cudaGetSymbolAddress((void**)&rowptr, g_rowptr);
    cudaGetSymbolAddress((void**)&deg,    g_deg);
    cudaGetSymbolAddress((void**)&edges,  g_edge_s);
    cudaGetSymbolAddress((void**)&w2t,    g_w2t);
    cudaGetSymbolAddress((void**)&w1t,    g_w1t);

    const int smem64   = (64 * BS_STRIDE + 2 * BM * AS_STRIDE) * 4;
    const int smemL    = 3 * 128 * TS_STRIDE * 2;
    const int smemLast = 2 * 128 * TS_STRIDE * 2;
    const int smemTab  = (H * H + 2 * (TROWS + 1) * H) * 4;
    cudaFuncSetAttribute(gemm_tf32<F_IN>,
                         cudaFuncAttributeMaxDynamicSharedMemorySize, smem64);
    cudaFuncSetAttribute(layer_gemm<false>,
                         cudaFuncAttributeMaxDynamicSharedMemorySize, smemL);
    cudaFuncSetAttribute(layer_gemm<true>,
                         cudaFuncAttributeMaxDynamicSharedMemorySize, smemLast);
    cudaFuncSetAttribute(table_kernel,
                         cudaFuncAttributeMaxDynamicSharedMemorySize, smemTab);

    // precompute: tables (value+delta, direct), transposed weights (+pool zero)
    table_kernel<<<L_LAYERS * (TAB / TROWS), H, smemTab>>>(Wf1, bf1, Wf2, bf2);
    wtrans_kernel<<<dim3(64, L_LAYERS), 256>>>(W2, W1_rest);

    // build CSR by dst (memset + count + wide shfl scan + scatter)
    int nb = (N + 1023) / 1024;
    cudaMemsetAsync(deg, 0, (size_t)N * sizeof(int));
    deg_count_kernel<<<(E / 4 + 256) / 256, 256>>>(edst, E);
    scan_bsum_kernel<<<nb, 1024>>>(N);
    scan_boff_kernel<<<1, 64>>>(nb, E);
    scan_final_kernel<<<nb, 1024>>>(N);
    scatter_kernel<<<(E / 4 + 256) / 256, 256>>>(esrc, edst, edge_dist, E);

    int gemm_blocks = (N + BM - 1) / BM;
    int agg_blocks  = (N + 7) / 8;

    // initial projection: proj = x @ W1_0 + b1_0 (fp16 out)
    gemm_tf32<F_IN><<<gemm_blocks, 256, smem64>>>(x, W1_0, b1_0, proj, N);

    for (int l = 0; l < L_LAYERS; l++) {
        agg_kernel<<<agg_blocks, 256>>>(table2 + (size_t)l * TAB * 2 * H,
                                        proj, rowptr, edges, agg, N);

        if (l < L_LAYERS - 1) {
            layer_gemm<false><<<gemm_blocks, 256, smemL>>>(
                agg,
                w2t + (size_t)l * H * H, b2 + (size_t)l * H,
                w1t + (size_t)l * H * H, b1_rest + (size_t)l * H,
                proj, nullptr, N);
        } else {
            layer_gemm<true><<<gemm_blocks, 256, smemLast>>>(
                agg, w2t + (size_t)l * H * H, b2 + (size_t)l * H,
                nullptr, nullptr, nullptr, gid, N);
        }
    }

    // FC + log_softmax
    readout_kernel<<<G_GRAPHS, H>>>(fcw, fcb, out);
}

// round 17
// speedup vs baseline: 1.2225x; 1.0150x over previous
#include <cuda_runtime.h>
#include <cuda_fp16.h>

// Problem constants (fixed by the reference)
#define N_NODES 50000
#define N_EDGES 800000
#define F_IN    64
#define H       128
#define L_LAYERS 4
#define G_GRAPHS 64
#define C_OUT   10
#define TAB     256           // filter table: L1-resident
#define GAMMA_C 10.0f

// ---------------- scratch (device globals: allocation-free) ----------------
__device__ __half g_proj[N_NODES * H];
__device__ __half g_agg [N_NODES * H];
__device__ __half g_table2[L_LAYERS * TAB * 2 * H];   // interleaved (4 val, 4 delta) groups
__device__ __half g_w2t[L_LAYERS * H * H];
__device__ __half g_w1t[(L_LAYERS - 1) * H * H];
__device__ float  g_pool[G_GRAPHS * H];
__device__ float  g_cnt [G_GRAPHS];
// CSR-by-dst scratch
__device__ int    g_deg   [N_NODES];
__device__ int    g_rowptr[N_NODES + 1];
__device__ int    g_cursor[N_NODES];
__device__ int    g_bsum  [64];
__device__ int    g_boff  [64];
__device__ int2   g_edge_s[N_EDGES];

// ---------------- small helpers ----------------
__device__ __forceinline__ float ssp(float v) {
    return fmaxf(v, 0.f) + log1pf(expf(-fabsf(v))) - 0.6931472f;
}

__device__ __forceinline__ unsigned f2tf32(float x) {
    unsigned u;
    asm("cvt.rna.tf32.f32 %0, %1;" : "=r"(u) : "f"(x));
    return u;
}

__device__ __forceinline__ void cp_async16(unsigned saddr, const void* gaddr, int szbytes) {
    asm volatile("cp.async.cg.shared.global [%0], [%1], 16, %2;"
                 :: "r"(saddr), "l"(gaddr), "r"(szbytes));
}

__device__ __forceinline__ void ldsm_x4(unsigned& r0, unsigned& r1, unsigned& r2, unsigned& r3,
                                        unsigned addr) {
    asm volatile("ldmatrix.sync.aligned.m8n8.x4.shared.b16 {%0,%1,%2,%3}, [%4];"
                 : "=r"(r0), "=r"(r1), "=r"(r2), "=r"(r3) : "r"(addr));
}

// ---------------- weight pre-transpose (fp16 [n][k]) + pool zeroing ----------------
__global__ void wtrans_kernel(const float* __restrict__ W2, const float* __restrict__ W1_rest) {
    int l = blockIdx.y;
    int i = blockIdx.x * 256 + threadIdx.x;   // 0..16383
    int k = i >> 7, n = i & 127;
    g_w2t[l * H * H + n * H + k] = __float2half_rn(W2[l * H * H + k * H + n]);
    if (l < L_LAYERS - 1)
        g_w1t[l * H * H + n * H + k] = __float2half_rn(W1_rest[l * H * H + k * H + n]);
    if (l == 0) {
        if (i < G_GRAPHS * H) g_pool[i] = 0.f;
        if (i < G_GRAPHS)     g_cnt[i]  = 0.f;
    }
}

// ---------------- CSR build ----------------
__global__ void deg_count_kernel(const int* __restrict__ dst, int E) {
    int i = blockIdx.x * blockDim.x + threadIdx.x;
    int e4 = i * 4;
    if (e4 + 3 < E) {
        int4 d = __ldg((const int4*)dst + i);
        atomicAdd(&g_deg[d.x], 1);
        atomicAdd(&g_deg[d.y], 1);
        atomicAdd(&g_deg[d.z], 1);
        atomicAdd(&g_deg[d.w], 1);
    } else {
        for (int e = e4; e < E; e++) atomicAdd(&g_deg[dst[e]], 1);
    }
}

__global__ void scan_bsum_kernel(int N) {
    __shared__ int ws[32];
    int t = threadIdx.x;
    int lane = t & 31, w = t >> 5;
    int i = blockIdx.x * 1024 + t;
    int v = (i < N) ? g_deg[i] : 0;
    #pragma unroll
    for (int o = 16; o > 0; o >>= 1) v += __shfl_down_sync(0xffffffffu, v, o);
    if (lane == 0) ws[w] = v;
    __syncthreads();
    if (w == 0) {
        int s = ws[lane];
        #pragma unroll
        for (int o = 16; o > 0; o >>= 1) s += __shfl_down_sync(0xffffffffu, s, o);
        if (lane == 0) g_bsum[blockIdx.x] = s;
    }
}

__global__ void scan_boff_kernel(int nb, int E) {
    __shared__ int sh[64];
    int t = threadIdx.x;
    int v = (t < nb) ? g_bsum[t] : 0;
    sh[t] = v;
    __syncthreads();
    #pragma unroll
    for (int ofs = 1; ofs < 64; ofs <<= 1) {
        int x = (t >= ofs) ? sh[t - ofs] : 0;
        __syncthreads();
        sh[t] += x;
        __syncthreads();
    }
    if (t < nb) g_boff[t] = sh[t] - v;
    if (t == 0) g_rowptr[N_NODES] = E;
}

__global__ void scan_final_kernel(int N) {
    __shared__ int ws[32];
    int t = threadIdx.x;
    int lane = t & 31, w = t >> 5;
    int i = blockIdx.x * 1024 + t;
    int v = (i < N) ? g_deg[i] : 0;
    int x = v;
    #pragma unroll
    for (int o = 1; o < 32; o <<= 1) {
        int y = __shfl_up_sync(0xffffffffu, x, o);
        if (lane >= o) x += y;
    }
    if (lane == 31) ws[w] = x;
    __syncthreads();
    if (w == 0) {
        int s = ws[lane];
        #pragma unroll
        for (int o = 1; o < 32; o <<= 1) {
            int y = __shfl_up_sync(0xffffffffu, s, o);
            if (lane >= o) s += y;
        }
        ws[lane] = s;
    }
    __syncthreads();
    int warpExcl = (w == 0) ? 0 : ws[w - 1];
    if (i < N) {
        int ex = x - v + warpExcl + g_boff[blockIdx.x];
        g_rowptr[i] = ex;
        g_cursor[i] = ex;
    }
}

__global__ void scatter_kernel(const int* __restrict__ src, const int* __restrict__ dst,
                               const float* __restrict__ dist, int E) {
    int i = blockIdx.x * blockDim.x + threadIdx.x;
    int e4 = i * 4;
    if (e4 + 3 < E) {
        int4   s = __ldg((const int4*)src + i);
        int4   d = __ldg((const int4*)dst + i);
        float4 v = __ldg((const float4*)dist + i);
        int p;
        p = atomicAdd(&g_cursor[d.x], 1); g_edge_s[p] = make_int2(s.x, __float_as_int(v.x));
        p = atomicAdd(&g_cursor[d.y], 1); g_edge_s[p] = make_int2(s.y, __float_as_int(v.y));
        p = atomicAdd(&g_cursor[d.z], 1); g_edge_s[p] = make_int2(s.z, __float_as_int(v.z));
        p = atomicAdd(&g_cursor[d.w], 1); g_edge_s[p] = make_int2(s.w, __float_as_int(v.w));
    } else {
        for (int e = e4; e < E; e++) {
            int p = atomicAdd(&g_cursor[dst[e]], 1);
            g_edge_s[p] = make_int2(src[e], __float_as_int(dist[e]));
        }
    }
}

// ---------------- filter table build (value+delta interleaved, direct) ----------------
#define TROWS 16
__global__ void table_kernel(const float* __restrict__ Wf1, const float* __restrict__ bf1,
                             const float* __restrict__ Wf2, const float* __restrict__ bf2) {
    extern __shared__ float ts[];
    float* wbuf = ts;
    float* rbfb = ts + H * H;
    float* hidb = rbfb + (TROWS + 1) * H;

    const int chunks = TAB / TROWS;
    int l  = blockIdx.x / chunks;
    int r0 = (blockIdx.x % chunks) * TROWS;
    int j  = threadIdx.x;
    float cj = j * (1.0f / (H - 1));

    #pragma unroll
    for (int r = 0; r <= TROWS; r++) {
        int rr = min(r0 + r, TAB - 1);
        float d = rr * (1.0f / (TAB - 1));
        float u = d - cj;
        rbfb[r * H + j] = expf(-GAMMA_C * u * u);
    }

    const float4* w1 = (const float4*)(Wf1 + (size_t)l * H * H);
    for (int i = j; i < H * H / 4; i += 128) ((float4*)wbuf)[i] = __ldg(w1 + i);
    __syncthreads();

    float b1v = bf1[l * H + j];
    float b2v = bf2[l * H + j];

    #pragma unroll 2
    for (int r = 0; r <= TROWS; r++) {
        float acc = b1v;
        #pragma unroll 8
        for (int i = 0; i < H; i++) acc = fmaf(rbfb[r * H + i], wbuf[i * H + j], acc);
        hidb[r * H + j] = ssp(acc);
    }
    __syncthreads();

    const float4* w2 = (const float4*)(Wf2 + (size_t)l * H * H);
    for (int i = j; i < H * H / 4; i += 128) ((float4*)wbuf)[i] = __ldg(w2 + i);
    __syncthreads();

    __half vh[TROWS + 1];
    #pragma unroll 2
    for (int r = 0; r <= TROWS; r++) {
        float acc = b2v;
        #pragma unroll 8
        for (int i = 0; i < H; i++) acc = fmaf(hidb[r * H + i], wbuf[i * H + j], acc);
        vh[r] = __float2half_rn(acc);
    }

    int grp = j >> 2, w = j & 3;
    #pragma unroll
    for (int r = 0; r < TROWS; r++) {
        __half* dst = g_table2 + ((size_t)l * TAB + r0 + r) * (2 * H);
        dst[grp * 8 + w]     = vh[r];
        dst[grp * 8 + 4 + w] = __hsub(vh[r + 1], vh[r]);
    }
}

// ---------------- GEMM tiling constants ----------------
#define BM 128
#define AS_STRIDE 36
#define BS_STRIDE 132
#define TS_STRIDE 136    // halves (272 B -> ldmatrix conflict-free)

// ---------------- pipelined tf32 GEMM (initial projection only, K=64) ----------------
template <int KDIM>
__global__ void __launch_bounds__(256, 2) gemm_tf32(const float* __restrict__ A,
                                                    const float* __restrict__ B,
                                                    const float* __restrict__ bias,
                                                    __half* __restrict__ C, int M) {
    constexpr int KITERS = KDIM / 32;
    extern __shared__ float smem[];
    float* Bs = smem;
    float* As = smem + KDIM * BS_STRIDE;

    int tid  = threadIdx.x;
    int lane = tid & 31;
    int wid  = tid >> 5;
    int wm   = wid >> 2;
    int wn   = wid & 3;
    int grp  = lane >> 2;
    int thr4 = lane & 3;
    int r0   = blockIdx.x * BM;

    auto stage_A = [&](int chunk, int buf) {
        float* dstbase = As + buf * (BM * AS_STRIDE);
        #pragma unroll
        for (int j = 0; j < 4; j++) {
            int idx = tid + j * 256;
            int row = idx >> 3;
            int k4  = idx & 7;
            int gr  = r0 + row;
            int grc = gr < M ? gr : 0;
            const float* gp = A + (size_t)grc * KDIM + chunk * 32 + k4 * 4;
            unsigned sa = (unsigned)__cvta_generic_to_shared(dstbase + row * AS_STRIDE + k4 * 4);
            cp_async16(sa, gp, (gr < M) ? 16 : 0);
        }
        asm volatile("cp.async.commit_group;");
    };

    stage_A(0, 0);
    if (KITERS > 1) stage_A(1, 1);

    #pragma unroll
    for (int i = tid; i < KDIM * 32; i += 256) {
        int k  = i >> 5;
        int n4 = i & 31;
        float4 v = *(const float4*)(B + (size_t)k * H + n4 * 4);
        float* d = Bs + k * BS_STRIDE + n4 * 4;
        d[0] = __uint_as_float(f2tf32(v.x));
        d[1] = __uint_as_float(f2tf32(v.y));
        d[2] = __uint_as_float(f2tf32(v.z));
        d[3] = __uint_as_float(f2tf32(v.w));
    }

    float c[4][4][4];
    #pragma unroll
    for (int i = 0; i < 4; i++)
        #pragma unroll
        for (int j = 0; j < 4; j++)
            #pragma unroll
            for (int r = 0; r < 4; r++) c[i][j][r] = 0.f;

    #pragma unroll
    for (int ki = 0; ki < KITERS; ki++) {
        if (ki == KITERS - 1) asm volatile("cp.async.wait_group 0;" ::: "memory");
        else                  asm volatile("cp.async.wait_group 1;" ::: "memory");
        __syncthreads();

        const float* Ab = As + (ki & 1) * (BM * AS_STRIDE);
        #pragma unroll
        for (int ks = 0; ks < 4; ks++) {
            unsigned a[4][4];
            #pragma unroll
            for (int am = 0; am < 4; am++) {
                const float* base = Ab + (size_t)(wm * 64 + am * 16 + grp) * AS_STRIDE + ks * 8 + thr4;
                a[am][0] = f2tf32(base[0]);
                a[am][1] = f2tf32(base[8 * AS_STRIDE]);
                a[am][2] = f2tf32(base[4]);
                a[am][3] = f2tf32(base[8 * AS_STRIDE + 4]);
            }
            unsigned b[4][2];
            #pragma unroll
            for (int an = 0; an < 4; an++) {
                const float* bb = Bs + (size_t)(ki * 32 + ks * 8 + thr4) * BS_STRIDE + wn * 32 + an * 8 + grp;
                b[an][0] = __float_as_uint(bb[0]);
                b[an][1] = __float_as_uint(bb[4 * BS_STRIDE]);
            }
            #pragma unroll
            for (int am = 0; am < 4; am++)
                #pragma unroll
                for (int an = 0; an < 4; an++) {
                    asm volatile(
                        "mma.sync.aligned.m16n8k8.row.col.f32.tf32.tf32.f32 "
                        "{%0,%1,%2,%3}, {%4,%5,%6,%7}, {%8,%9}, {%0,%1,%2,%3};"
                        : "+f"(c[am][an][0]), "+f"(c[am][an][1]),
                          "+f"(c[am][an][2]), "+f"(c[am][an][3])
                        : "r"(a[am][0]), "r"(a[am][1]), "r"(a[am][2]), "r"(a[am][3]),
                          "r"(b[an][0]), "r"(b[an][1]));
                }
        }

        if (ki + 2 < KITERS) {
            __syncthreads();
            stage_A(ki + 2, ki & 1);
        }
    }

    #pragma unroll
    for (int an = 0; an < 4; an++) {
        int col = wn * 32 + an * 8 + 2 * thr4;
        float2 bv = *(const float2*)(bias + col);
        #pragma unroll
        for (int am = 0; am < 4; am++) {
            int row0 = r0 + wm * 64 + am * 16 + grp;
            if (row0 < M)
                *(__half2*)(C + (size_t)row0 * H + col) =
                    __floats2half2_rn(c[am][an][0] + bv.x, c[am][an][1] + bv.y);
            if (row0 + 8 < M)
                *(__half2*)(C + (size_t)(row0 + 8) * H + col) =
                    __floats2half2_rn(c[am][an][2] + bv.x, c[am][an][3] + bv.y);
        }
    }
}

// ---------------- fp16 layer GEMM (ldmatrix fragments, pretransposed weights) ----------------
// !LAST: P = relu(A@W2 + b2) @ W1 + b1
//  LAST: pool += relu(A@W2 + b2) per graph (direct red), counts per graph
template <bool LAST>
__global__ void __launch_bounds__(256, 2) layer_gemm(const __half* __restrict__ A,
                                                     const __half* __restrict__ w2t,
                                                     const float* __restrict__ b2,
                                                     const __half* __restrict__ w1t,
                                                     const float* __restrict__ b1,
                                                     __half* __restrict__ P,
                                                     const int* __restrict__ gid, int M) {
    extern __shared__ __half shh[];
    __half* Ah  = shh;
    __half* W2t = shh + 128 * TS_STRIDE;
    __half* W1t = W2t + 128 * TS_STRIDE;

    int tid  = threadIdx.x;
    int lane = tid & 31;
    int wid  = tid >> 5;
    int wm   = wid >> 2;
    int wn   = wid & 3;
    int grp  = lane >> 2;
    int thr4 = lane & 3;
    int r0   = blockIdx.x * BM;

    // group 0: A + W2 (needed for GEMM1)
    #pragma unroll
    for (int j = 0; j < 8; j++) {
        int cidx = tid + j * 256;
        int row  = cidx >> 4;
        int c16  = cidx & 15;
        int gr   = r0 + row;
        int grc  = gr < M ? gr : 0;
        cp_async16((unsigned)__cvta_generic_to_shared(Ah + row * TS_STRIDE + c16 * 8),
                   A + (size_t)grc * H + c16 * 8, (gr < M) ? 16 : 0);
    }
    #pragma unroll
    for (int j = 0; j < 8; j++) {
        int cidx = tid + j * 256;
        int row  = cidx >> 4;
        int c16  = cidx & 15;
        cp_async16((unsigned)__cvta_generic_to_shared(W2t + row * TS_STRIDE + c16 * 8),
                   w2t + (size_t)row * H + c16 * 8, 16);
    }
    asm volatile("cp.async.commit_group;");
    // group 1: W1 (needed only for GEMM2)
    if constexpr (!LAST) {
        #pragma unroll
        for (int j = 0; j < 8; j++) {
            int cidx = tid + j * 256;
            int row  = cidx >> 4;
            int c16  = cidx & 15;
            cp_async16((unsigned)__cvta_generic_to_shared(W1t + row * TS_STRIDE + c16 * 8),
                       w1t + (size_t)row * H + c16 * 8, 16);
        }
        asm volatile("cp.async.commit_group;");
        asm volatile("cp.async.wait_group 1;" ::: "memory");   // A+W2 ready; W1 in flight
    } else {
        asm volatile("cp.async.wait_group 0;" ::: "memory");
    }
    __syncthreads();

    unsigned AhU  = (unsigned)__cvta_generic_to_shared(Ah);
    unsigned W2tU = (unsigned)__cvta_generic_to_shared(W2t);

    int rowA  = lane & 15;
    int colA8 = (lane >> 4) * 8;
    int rowB  = (lane & 7) + ((lane >> 4) & 1) * 8;
    int colB8 = ((lane >> 3) & 1) * 8;

    float c[4][4][4];
    #pragma unroll
    for (int i = 0; i < 4; i++)
        #pragma unroll
        for (int j = 0; j < 4; j++)
            #pragma unroll
            for (int r = 0; r < 4; r++) c[i][j][r] = 0.f;

    #pragma unroll
    for (int kc = 0; kc < 8; kc++) {
        unsigned a[4][4];
        #pragma unroll
        for (int am = 0; am < 4; am++) {
            unsigned addr = AhU + (unsigned)(((wm * 64 + am * 16 + rowA) * TS_STRIDE
                                              + kc * 16 + colA8) * 2);
            ldsm_x4(a[am][0], a[am][1], a[am][2], a[am][3], addr);
        }
        unsigned b[4][2];
        #pragma unroll
        for (int anp = 0; anp < 2; anp++) {
            int n0 = wn * 32 + anp * 16;
            unsigned addr = W2tU + (unsigned)(((n0 + rowB) * TS_STRIDE + kc * 16 + colB8) * 2);
            ldsm_x4(b[2 * anp][0], b[2 * anp][1], b[2 * anp + 1][0], b[2 * anp + 1][1], addr);
        }
        #pragma unroll
        for (int am = 0; am < 4; am++)
            #pragma unroll
            for (int an = 0; an < 4; an++) {
                asm volatile(
                    "mma.sync.aligned.m16n8k16.row.col.f32.f16.f16.f32 "
                    "{%0,%1,%2,%3}, {%4,%5,%6,%7}, {%8,%9}, {%0,%1,%2,%3};"
                    : "+f"(c[am][an][0]), "+f"(c[am][an][1]),
                      "+f"(c[am][an][2]), "+f"(c[am][an][3])
                    : "r"(a[am][0]), "r"(a[am][1]), "r"(a[am][2]), "r"(a[am][3]),
                      "r"(b[an][0]), "r"(b[an][1]));
            }
    }

    if constexpr (LAST) {
        #pragma unroll
        for (int am = 0; am < 4; am++) {
            int row0 = r0 + wm * 64 + am * 16 + grp;
            int g0 = (row0 < M)     ? __ldg(gid + row0)     : 0;
            int g1 = (row0 + 8 < M) ? __ldg(gid + row0 + 8) : 0;
            #pragma unroll
            for (int an = 0; an < 4; an++) {
                int col = wn * 32 + an * 8 + 2 * thr4;
                float2 bv = *(const float2*)(b2 + col);
                float o0x = fmaxf(c[am][an][0] + bv.x, 0.f);
                float o0y = fmaxf(c[am][an][1] + bv.y, 0.f);
                float o1x = fmaxf(c[am][an][2] + bv.x, 0.f);
                float o1y = fmaxf(c[am][an][3] + bv.y, 0.f);
                if (row0 < M) {
                    float* p = g_pool + (size_t)g0 * H + col;
                    asm volatile("red.global.add.v2.f32 [%0], {%1,%2};"
                                 :: "l"(p), "f"(o0x), "f"(o0y) : "memory");
                }
                if (row0 + 8 < M) {
                    float* p = g_pool + (size_t)g1 * H + col;
                    asm volatile("red.global.add.v2.f32 [%0], {%1,%2};"
                                 :: "l"(p), "f"(o1x), "f"(o1y) : "memory");
                }
            }
            if (wn == 0 && thr4 == 0) {
                if (row0 < M)     atomicAdd(&g_cnt[g0], 1.0f);
                if (row0 + 8 < M) atomicAdd(&g_cnt[g1], 1.0f);
            }
        }
        return;
    }

    __syncthreads();

    #pragma unroll
    for (int an = 0; an < 4; an++) {
        int col = wn * 32 + an * 8 + 2 * thr4;
        float2 bv = *(const float2*)(b2 + col);
        #pragma unroll
        for (int am = 0; am < 4; am++) {
            int r = wm * 64 + am * 16 + grp;
            *(__half2*)(Ah + (size_t)r * TS_STRIDE + col) =
                __floats2half2_rn(fmaxf(c[am][an][0] + bv.x, 0.f),
                                  fmaxf(c[am][an][1] + bv.y, 0.f));
            *(__half2*)(Ah + (size_t)(r + 8) * TS_STRIDE + col) =
                __floats2half2_rn(fmaxf(c[am][an][2] + bv.x, 0.f),
                                  fmaxf(c[am][an][3] + bv.y, 0.f));
        }
    }
    asm volatile("cp.async.wait_group 0;" ::: "memory");   // W1 landed
    __syncthreads();

    unsigned W1tU = (unsigned)__cvta_generic_to_shared(W1t);

    float p[4][4][4];
    #pragma unroll
    for (int i = 0; i < 4; i++)
        #pragma unroll
        for (int j = 0; j < 4; j++)
            #pragma unroll
            for (int r = 0; r < 4; r++) p[i][j][r] = 0.f;

    #pragma unroll
    for (int kc = 0; kc < 8; kc++) {
        unsigned a[4][4];
        #pragma unroll
        for (int am = 0; am < 4; am++) {
            unsigned addr = AhU + (unsigned)(((wm * 64 + am * 16 + rowA) * TS_STRIDE
                                              + kc * 16 + colA8) * 2);
            ldsm_x4(a[am][0], a[am][1], a[am][2], a[am][3], addr);
        }
        unsigned b[4][2];
        #pragma unroll
        for (int anp = 0; anp < 2; anp++) {
            int n0 = wn * 32 + anp * 16;
            unsigned addr = W1tU + (unsigned)(((n0 + rowB) * TS_STRIDE + kc * 16 + colB8) * 2);
            ldsm_x4(b[2 * anp][0], b[2 * anp][1], b[2 * anp + 1][0], b[2 * anp + 1][1], addr);
        }
        #pragma unroll
        for (int am = 0; am < 4; am++)
            #pragma unroll
            for (int an = 0; an < 4; an++) {
                asm volatile(
                    "mma.sync.aligned.m16n8k16.row.col.f32.f16.f16.f32 "
                    "{%0,%1,%2,%3}, {%4,%5,%6,%7}, {%8,%9}, {%0,%1,%2,%3};"
                    : "+f"(p[am][an][0]), "+f"(p[am][an][1]),
                      "+f"(p[am][an][2]), "+f"(p[am][an][3])
                    : "r"(a[am][0]), "r"(a[am][1]), "r"(a[am][2]), "r"(a[am][3]),
                      "r"(b[an][0]), "r"(b[an][1]));
            }
    }

    #pragma unroll
    for (int an = 0; an < 4; an++) {
        int col = wn * 32 + an * 8 + 2 * thr4;
        float2 bv = *(const float2*)(b1 + col);
        #pragma unroll
        for (int am = 0; am < 4; am++) {
            int row0 = r0 + wm * 64 + am * 16 + grp;
            if (row0 < M)
                *(__half2*)(P + (size_t)row0 * H + col) =
                    __floats2half2_rn(p[am][an][0] + bv.x, p[am][an][1] + bv.y);
            if (row0 + 8 < M)
                *(__half2*)(P + (size_t)(row0 + 8) * H + col) =
                    __floats2half2_rn(p[am][an][2] + bv.x, p[am][an][3] + bv.y);
        }
    }
}

// ---------------- CSR aggregation: warp/node, 2-edge ILP, value+delta table ----------------
__global__ void __launch_bounds__(512) agg_kernel(const __half* __restrict__ table2,
                           const __half* __restrict__ proj,
                           const int*   __restrict__ rowptr,
                           const int2*  __restrict__ edges,
                           __half*      __restrict__ agg, int N) {
    int n = blockIdx.x * 16 + (threadIdx.x >> 5);
    if (n >= N) return;
    int lane = threadIdx.x & 31;

    int beg = __ldg(rowptr + n);
    int end = __ldg(rowptr + n + 1);

    float ax = 0.f, ay = 0.f, az = 0.f, aw = 0.f;

    auto ldidx = [&](int j, int& s, int& k, float& fr) {
        int2 v = __ldg(edges + j);
        s = v.x;
        float d = __int_as_float(v.y);
        float pos = d * (float)(TAB - 1);
        int kk = (int)pos;
        kk = min(max(kk, 0), TAB - 2);
        fr = pos - (float)kk;
        k = kk;
    };

    auto edge_msg = [&](const uint4& q, const uint2& hp, float fr,
                        __half2& m0, __half2& m1) {
        __half2 fr2 = __float2half2_rn(fr);
        __half2 v0 = *(const __half2*)&q.x;
        __half2 v1 = *(const __half2*)&q.y;
        __half2 d0 = *(const __half2*)&q.z;
        __half2 d1 = *(const __half2*)&q.w;
        __half2 pa = *(const __half2*)&hp.x;
        __half2 pb = *(const __half2*)&hp.y;
        m0 = __hmul2(__hfma2(fr2, d0, v0), pa);
        m1 = __hmul2(__hfma2(fr2, d1, v1), pb);
    };

    int sA = 0, kA = 0, sB = 0, kB = 0;
    float frA = 0.f, frB = 0.f;
    if (beg < end)     ldidx(beg,     sA, kA, frA);
    if (beg + 1 < end) ldidx(beg + 1, sB, kB, frB);

    for (int i = beg; i < end; i += 2) {
        bool has2 = (i + 1 < end);
        int sC = 0, kC = 0, sD = 0, kD = 0;
        float frC = 0.f, frD = 0.f;
        if (i + 2 < end) ldidx(i + 2, sC, kC, frC);
        if (i + 3 < end) ldidx(i + 3, sD, kD, frD);

        // long-latency L2 gathers first, then (mostly L1-hit) table rows
        uint2 hpA = __ldg((const uint2*)(proj + (size_t)sA * H) + lane);
        uint2 hpB;
        if (has2) hpB = __ldg((const uint2*)(proj + (size_t)sB * H) + lane);
        uint4 qA = __ldg((const uint4*)(table2 + (size_t)kA * (2 * H)) + lane);
        uint4 qB;
        if (has2) qB = __ldg((const uint4*)(table2 + (size_t)kB * (2 * H)) + lane);

        __half2 mA0, mA1;
        edge_msg(qA, hpA, frA, mA0, mA1);
        if (has2) {
            __half2 mB0, mB1;
            edge_msg(qB, hpB, frB, mB0, mB1);
            mA0 = __hadd2(mA0, mB0);
            mA1 = __hadd2(mA1, mB1);
        }
        float2 f0 = __half22float2(mA0);
        float2 f1 = __half22float2(mA1);
        ax += f0.x; ay += f0.y; az += f1.x; aw += f1.y;

        sA = sC; kA = kC; frA = frC;
        sB = sD; kB = kD; frB = frD;
    }

    uint2 o;
    __half2 h01 = __floats2half2_rn(ax, ay);
    __half2 h23 = __floats2half2_rn(az, aw);
    o.x = *(unsigned*)&h01;
    o.y = *(unsigned*)&h23;
    *(uint2*)(agg + (size_t)n * H + lane * 4) = o;
}

// ---------------- readout: mean, FC, log_softmax ----------------
__global__ void readout_kernel(const float* __restrict__ fcw, const float* __restrict__ fcb,
                               float* __restrict__ out) {
    int g = blockIdx.x;
    int t = threadIdx.x;
    __shared__ float p[H];
    __shared__ float logits[C_OUT];

    float c = fmaxf(g_cnt[g], 1.0f);
    p[t] = g_pool[(size_t)g * H + t] / c;
    __syncthreads();

    if (t < C_OUT) {
        float acc = fcb[t];
        #pragma unroll 8
        for (int h = 0; h < H; h++) acc = fmaf(p[h], fcw[h * C_OUT + t], acc);
        logits[t] = acc;
    }
    __syncthreads();

    if (t == 0) {
        float mx = -1e30f;
        for (int i = 0; i < C_OUT; i++) mx = fmaxf(mx, logits[i]);
        float se = 0.f;
        for (int i = 0; i < C_OUT; i++) se += expf(logits[i] - mx);
        float lse = mx + logf(se);
        for (int i = 0; i < C_OUT; i++) out[g * C_OUT + i] = logits[i] - lse;
    }
}

// ---------------- launch ----------------
extern "C" void kernel_launch(void* const* d_in, const int* in_sizes, int n_in,
                              void* d_out, int out_size) {
    const float* x         = (const float*)d_in[0];
    const float* edge_dist = (const float*)d_in[1];
    const int*   esrc      = (const int*)  d_in[2];
    const int*   edst      = (const int*)  d_in[3];
    const int*   gid       = (const int*)  d_in[4];
    const float* W1_0      = (const float*)d_in[5];
    const float* b1_0      = (const float*)d_in[6];
    const float* W1_rest   = (const float*)d_in[7];
    const float* b1_rest   = (const float*)d_in[8];
    const float* Wf1       = (const float*)d_in[9];
    const float* bf1       = (const float*)d_in[10];
    const float* Wf2       = (const float*)d_in[11];
    const float* bf2       = (const float*)d_in[12];
    const float* W2        = (const float*)d_in[13];
    const float* b2        = (const float*)d_in[14];
    const float* fcw       = (const float*)d_in[15];
    const float* fcb       = (const float*)d_in[16];
    float* out = (float*)d_out;

    int E = in_sizes[1];
    int N = in_sizes[4];

    __half *proj, *agg, *table2, *w2t, *w1t;
    int *rowptr, *deg;
    int2 *edges;
    cudaGetSymbolAddress((void**)&proj,   g_proj);
    cudaGetSymbolAddress((void**)&agg,    g_agg);
    cudaGetSymbolAddress((void**)&table2, g_table2);
    cudaGetSymbolAddress((void**)&rowptr, g_rowptr);
    cudaGetSymbolAddress((void**)&deg,    g_deg);
    cudaGetSymbolAddress((void**)&edges,  g_edge_s);
    cudaGetSymbolAddress((void**)&w2t,    g_w2t);
    cudaGetSymbolAddress((void**)&w1t,    g_w1t);

    const int smem64   = (64 * BS_STRIDE + 2 * BM * AS_STRIDE) * 4;
    const int smemL    = 3 * 128 * TS_STRIDE * 2;
    const int smemLast = 2 * 128 * TS_STRIDE * 2;
    const int smemTab  = (H * H + 2 * (TROWS + 1) * H) * 4;
    cudaFuncSetAttribute(gemm_tf32<F_IN>,
                         cudaFuncAttributeMaxDynamicSharedMemorySize, smem64);
    cudaFuncSetAttribute(layer_gemm<false>,
                         cudaFuncAttributeMaxDynamicSharedMemorySize, smemL);
    cudaFuncSetAttribute(layer_gemm<true>,
                         cudaFuncAttributeMaxDynamicSharedMemorySize, smemLast);
    cudaFuncSetAttribute(table_kernel,
                         cudaFuncAttributeMaxDynamicSharedMemorySize, smemTab);

    // precompute: tables (value+delta, direct), transposed weights (+pool zero)
    table_kernel<<<L_LAYERS * (TAB / TROWS), H, smemTab>>>(Wf1, bf1, Wf2, bf2);
    wtrans_kernel<<<dim3(64, L_LAYERS), 256>>>(W2, W1_rest);

    // build CSR by dst (memset + count + wide shfl scan + scatter)
    int nb = (N + 1023) / 1024;
    cudaMemsetAsync(deg, 0, (size_t)N * sizeof(int));
    deg_count_kernel<<<(E / 4 + 256) / 256, 256>>>(edst, E);
    scan_bsum_kernel<<<nb, 1024>>>(N);
    scan_boff_kernel<<<1, 64>>>(nb, E);
    scan_final_kernel<<<nb, 1024>>>(N);
    scatter_kernel<<<(E / 4 + 256) / 256, 256>>>(esrc, edst, edge_dist, E);

    int gemm_blocks = (N + BM - 1) / BM;
    int agg_blocks  = (N + 15) / 16;

    // initial projection: proj = x @ W1_0 + b1_0 (fp16 out)
    gemm_tf32<F_IN><<<gemm_blocks, 256, smem64>>>(x, W1_0, b1_0, proj, N);

    for (int l = 0; l < L_LAYERS; l++) {
        agg_kernel<<<agg_blocks, 512>>>(table2 + (size_t)l * TAB * 2 * H,
                                        proj, rowptr, edges, agg, N);

        if (l < L_LAYERS - 1) {
            layer_gemm<false><<<gemm_blocks, 256, smemL>>>(
                agg,
                w2t + (size_t)l * H * H, b2 + (size_t)l * H,
                w1t + (size_t)l * H * H, b1_rest + (size_t)l * H,
                proj, nullptr, N);
        } else {
            layer_gemm<true><<<gemm_blocks, 256, smemLast>>>(
                agg, w2t + (size_t)l * H * H, b2 + (size_t)l * H,
                nullptr, nullptr, nullptr, gid, N);
        }
    }

    // FC + log_softmax
    readout_kernel<<<G_GRAPHS, H>>>(fcw, fcb, out);
}